// round 11
// baseline (speedup 1.0000x reference)
#include <cuda_runtime.h>
#include <cuda_bf16.h>
#include <math.h>
#include <stdint.h>

#define NJ 24
#define NV 20000
#define NG 2
#define HID 128
#define EPSV 1e-8f
#define TPB 256
#define MTILE 128
#define WSTRIDE 136   // padded row stride (elements) for conflict-free LDS

// smem layout (bytes)
#define OFF_ACT_HI 0
#define OFF_ACT_LO 34816
#define OFF_W_HI   69632
#define OFF_W_LO   104448
#define OFF_F32    139264   // w0s[896], b0s[128], b1s[128], b2s[128], w3s[128]
#define SMEM_BYTES (139264 + (896 + 4 * 128) * 4)

__device__ float g_c[NJ][4];
__device__ float g_geom[NJ][NG][16];
__device__ float g_pred[NJ][NV];
// [layer][hi/lo][j] transposed weights Wt[n][k], stride 136, bf16
__device__ __nv_bfloat16 g_Wt[2][2][NJ][HID * WSTRIDE];

__device__ __forceinline__ float sp100(float x) {
    float t = 100.0f * x;
    if (t > 20.0f) return x;
    return log1pf(expf(t)) * 0.01f;
}
__device__ __forceinline__ float sp100f(float x) {
    return fmaxf(x, 0.0f) + __logf(1.0f + __expf(-fabsf(100.0f * x))) * 0.01f;
}
__device__ __forceinline__ float ra_elu(float x) {
    return (x - 1.0f) > 0.0f ? x : expf(x - 1.0f);
}
__device__ __forceinline__ uint32_t packsplit_hi(float a, float b, uint32_t& lo) {
    __nv_bfloat16 ha = __float2bfloat16_rn(a);
    __nv_bfloat16 hb = __float2bfloat16_rn(b);
    __nv_bfloat16 la = __float2bfloat16_rn(a - __bfloat162float(ha));
    __nv_bfloat16 lb = __float2bfloat16_rn(b - __bfloat162float(hb));
    lo = (uint32_t)__bfloat16_as_ushort(la) | ((uint32_t)__bfloat16_as_ushort(lb) << 16);
    return (uint32_t)__bfloat16_as_ushort(ha) | ((uint32_t)__bfloat16_as_ushort(hb) << 16);
}

__device__ __forceinline__ void mma16816(float* c, const uint32_t* a, const uint32_t* b) {
    asm volatile(
        "mma.sync.aligned.m16n8k16.row.col.f32.bf16.bf16.f32 "
        "{%0,%1,%2,%3}, {%4,%5,%6,%7}, {%8,%9}, {%0,%1,%2,%3};"
        : "+f"(c[0]), "+f"(c[1]), "+f"(c[2]), "+f"(c[3])
        : "r"(a[0]), "r"(a[1]), "r"(a[2]), "r"(a[3]), "r"(b[0]), "r"(b[1]));
}
__device__ __forceinline__ uint32_t lds32(const __nv_bfloat16* p) {
    return *(const uint32_t*)p;
}

// ---------------------------------------------------------------------------
// Per-part precompute (cond MLP + blending constants)
// ---------------------------------------------------------------------------
__global__ void pre_kernel(const float* __restrict__ Bcond, const float* __restrict__ Bneigh,
                           const float* __restrict__ alpha, const float* __restrict__ beta,
                           const float* __restrict__ cW0, const float* __restrict__ cb0,
                           const float* __restrict__ cW1, const float* __restrict__ cb1,
                           const float* __restrict__ cW2, const float* __restrict__ cb2)
{
    int j = blockIdx.x, lane = threadIdx.x;
    __shared__ float c0[16], c1[16];
    if (lane < 16) {
        float s = cb0[j * 16 + lane];
        const float* w = cW0 + (size_t)j * 288 * 16 + lane;
        const float* cond = Bcond + j * 288;
        for (int k = 0; k < 288; k++) s += cond[k] * w[k * 16];
        c0[lane] = sp100(s);
    }
    __syncthreads();
    if (lane < 16) {
        float s = cb1[j * 16 + lane];
        const float* w = cW1 + j * 256 + lane;
        for (int k = 0; k < 16; k++) s += c0[k] * w[k * 16];
        c1[lane] = sp100(s);
    }
    __syncthreads();
    if (lane < 4) {
        float s = cb2[j * 4 + lane];
        const float* w = cW2 + j * 64 + lane;
        for (int k = 0; k < 16; k++) s += c1[k] * w[k * 4];
        g_c[j][lane] = s;
    }
    if (lane < NG) {
        int gi = lane;
        const float* bn = Bneigh + ((j * NG + gi) * 5) * 3;
        float Jt[3] = { bn[0], bn[1], bn[2] };
        float Jc[3] = { bn[3], bn[4], bn[5] };
        float Jo[3] = { bn[6], bn[7], bn[8] };
        float Jp[3] = { bn[9], bn[10], bn[11] };
        int bt = (int)bn[12], bo = (int)bn[13];
        float a_n = ra_elu(alpha[bo * NJ + bt]);
        float a_s = ra_elu(alpha[bt * NJ + bo]);
        float be_n = beta[bo * NJ + bt];
        float be_s = beta[bt * NJ + bo];
        float nb_n = 0.f, nb_s = 0.f;
        for (int d = 0; d < 3; d++) {
            float tn = Jo[d] - Jc[d]; nb_n += tn * tn;
            float ts = Jt[d] - Jc[d]; nb_s += ts * ts;
        }
        nb_n = sqrtf(nb_n); nb_s = sqrtf(nb_s);
        float vn[3], vs[3];
        float f1 = nb_n / (nb_n + nb_s + EPSV);
        for (int d = 0; d < 3; d++) vn[d] = (Jo[d] - Jt[d]) * f1;
        float f2 = nb_s / (nb_n + EPSV);
        for (int d = 0; d < 3; d++) vs[d] = -vn[d] * f2;
        float n_n = 0.f, n_s = 0.f;
        for (int d = 0; d < 3; d++) { n_n += vn[d] * vn[d]; n_s += vs[d] * vs[d]; }
        n_n = sqrtf(n_n); n_s = sqrtf(n_s);
        float cn = a_n / ((n_n + EPSV) * (n_n + EPSV));
        float cs = a_s / ((n_s + EPSV) * (n_s + EPSV));
        float* gg = g_geom[j][gi];
        for (int d = 0; d < 3; d++) gg[d] = Jo[d] - vn[d];
        for (int d = 0; d < 3; d++) gg[3 + d] = vn[d] * cn - vs[d] * cs;
        gg[6] = be_n - be_s;
        for (int d = 0; d < 3; d++) gg[7 + d] = Jp[d];
        for (int d = 0; d < 3; d++) gg[10 + d] = Jc[d];
    }
}

// ---------------------------------------------------------------------------
// Weight conversion: fp32 W[k][n] -> bf16 hi/lo transposed Wt[n][k], stride 136
// ---------------------------------------------------------------------------
__global__ void wconv_kernel(const float* __restrict__ W1, const float* __restrict__ W2) {
    int j = blockIdx.x, layer = blockIdx.y;
    const float* W = (layer == 0 ? W1 : W2) + (size_t)j * HID * HID;
    __nv_bfloat16* dh = &g_Wt[layer][0][j][0];
    __nv_bfloat16* dl = &g_Wt[layer][1][j][0];
    for (int idx = threadIdx.x; idx < HID * WSTRIDE; idx += blockDim.x) {
        int n = idx / WSTRIDE, k = idx - n * WSTRIDE;
        if (k < HID) {
            float w = W[k * HID + n];
            __nv_bfloat16 h = __float2bfloat16_rn(w);
            __nv_bfloat16 l = __float2bfloat16_rn(w - __bfloat162float(h));
            dh[idx] = h; dl[idx] = l;
        } else {
            dh[idx] = __float2bfloat16_rn(0.f);
            dl[idx] = __float2bfloat16_rn(0.f);
        }
    }
}

// ---------------------------------------------------------------------------
// Main kernel: 128 points x 1 part per CTA, mma.sync bf16 3-pass hidden layers
// ---------------------------------------------------------------------------
__global__ __launch_bounds__(TPB, 1) void main_kernel(
    const float* __restrict__ pts, const float* __restrict__ Btr, const float* __restrict__ Brot,
    const float* __restrict__ W0, const float* __restrict__ b0,
    const float* __restrict__ b1, const float* __restrict__ b2,
    const float* __restrict__ W3, const float* __restrict__ b3)
{
    extern __shared__ char sm[];
    __nv_bfloat16* actHi = (__nv_bfloat16*)(sm + OFF_ACT_HI);
    __nv_bfloat16* actLo = (__nv_bfloat16*)(sm + OFF_ACT_LO);
    __nv_bfloat16* wHi   = (__nv_bfloat16*)(sm + OFF_W_HI);
    __nv_bfloat16* wLo   = (__nv_bfloat16*)(sm + OFF_W_LO);
    float* w0s = (float*)(sm + OFF_F32);
    float* b0s = w0s + 896;
    float* b1s = b0s + 128;
    float* b2s = b1s + 128;
    float* w3s = b2s + 128;

    int tid = threadIdx.x;
    int j = blockIdx.y;
    int v0 = blockIdx.x * MTILE;
    int w = tid >> 5, lane = tid & 31;
    int g = lane >> 2, tig = lane & 3;

    // ---- stage layer-1 weights + w0 + biases ----
    {
        const uint4* s1 = (const uint4*)&g_Wt[0][0][j][0];
        const uint4* s2 = (const uint4*)&g_Wt[0][1][j][0];
        uint4* d1 = (uint4*)wHi;
        uint4* d2 = (uint4*)wLo;
        for (int i = tid; i < (HID * WSTRIDE) / 8; i += TPB) { d1[i] = s1[i]; d2[i] = s2[i]; }
        for (int i = tid; i < 896; i += TPB) w0s[i] = W0[j * 896 + i];
        if (tid < 128) {
            b0s[tid] = b0[j * 128 + tid];
            b1s[tid] = b1[j * 128 + tid];
            b2s[tid] = b2[j * 128 + tid];
            w3s[tid] = W3[j * 128 + tid];
        }
    }

    // ---- geometry (both halves of the block compute the same row redundantly) ----
    int m = tid & (MTILE - 1);
    int half = tid >> 7;
    int v = v0 + m;
    int vc = v < NV ? v : NV - 1;
    float xk[7];
    {
        float px = pts[vc * 3 + 0] - Btr[j * 3 + 0];
        float py = pts[vc * 3 + 1] - Btr[j * 3 + 1];
        float pz = pts[vc * 3 + 2] - Btr[j * 3 + 2];
        const float* R = Brot + j * 9;
        float plx = R[0] * px + R[3] * py + R[6] * pz;
        float ply = R[1] * px + R[4] * py + R[7] * pz;
        float plz = R[2] * px + R[5] * py + R[8] * pz;
        float ox = 0.f, oy = 0.f, oz = 0.f;
        #pragma unroll
        for (int gi = 0; gi < NG; gi++) {
            const float* gg = g_geom[j][gi];
            float dx = plx - gg[0], dy = ply - gg[1], dz = plz - gg[2];
            float arg = dx * gg[3] + dy * gg[4] + dz * gg[5] + gg[6];
            float ww = 1.0f / (1.0f + expf(-arg));
            float ax = -gg[7] * ww, ay = -gg[8] * ww, az = -gg[9] * ww;
            float ang = sqrtf(ax * ax + ay * ay + az * az);
            float inv = (ang < 1e-12f) ? 1.0f : (1.0f / ang);
            float ux = ax * inv, uy = ay * inv, uz = az * inv;
            float cc = cosf(ang), ss = sinf(ang);
            float C = 1.0f - cc;
            float qx = plx - gg[10], qy = ply - gg[11], qz = plz - gg[12];
            float rx = (cc + ux * ux * C) * qx + (ux * uy * C - uz * ss) * qy + (ux * uz * C + uy * ss) * qz;
            float ry = (uy * ux * C + uz * ss) * qx + (cc + uy * uy * C) * qy + (uy * uz * C - ux * ss) * qz;
            float rz = (uz * ux * C - uy * ss) * qx + (uz * uy * C + ux * ss) * qy + (cc + uz * uz * C) * qz;
            ox += rx + gg[10] - plx;
            oy += ry + gg[11] - ply;
            oz += rz + gg[12] - plz;
        }
        xk[0] = plx + ox; xk[1] = ply + oy; xk[2] = plz + oz;
        xk[3] = g_c[j][0]; xk[4] = g_c[j][1]; xk[5] = g_c[j][2]; xk[6] = g_c[j][3];
    }
    __syncthreads();   // weights + biases staged

    // ---- layer0 (7 -> 128): each half computes 64 outputs of its row ----
    {
        int nbeg = half * 64;
        #pragma unroll
        for (int n = 0; n < 64; n += 2) {
            int nn = nbeg + n;
            float s0 = b0s[nn], s1 = b0s[nn + 1];
            #pragma unroll
            for (int k = 0; k < 7; k++) {
                s0 += xk[k] * w0s[k * 128 + nn];
                s1 += xk[k] * w0s[k * 128 + nn + 1];
            }
            uint32_t lo;
            uint32_t hi = packsplit_hi(sp100f(s0), sp100f(s1), lo);
            *(uint32_t*)(actHi + m * WSTRIDE + nn) = hi;
            *(uint32_t*)(actLo + m * WSTRIDE + nn) = lo;
        }
    }
    __syncthreads();

    int m0 = w * 16 + g;   // mma row base for this thread
    float acc[16][4];

    // ================= layer 1 =================
    #pragma unroll
    for (int nt = 0; nt < 16; nt++)
        #pragma unroll
        for (int q = 0; q < 4; q++) acc[nt][q] = 0.f;

    #pragma unroll
    for (int kk = 0; kk < 8; kk++) {
        int c = kk * 16 + tig * 2;
        uint32_t ah[4], al[4];
        ah[0] = lds32(actHi + m0 * WSTRIDE + c);
        ah[1] = lds32(actHi + (m0 + 8) * WSTRIDE + c);
        ah[2] = lds32(actHi + m0 * WSTRIDE + c + 8);
        ah[3] = lds32(actHi + (m0 + 8) * WSTRIDE + c + 8);
        al[0] = lds32(actLo + m0 * WSTRIDE + c);
        al[1] = lds32(actLo + (m0 + 8) * WSTRIDE + c);
        al[2] = lds32(actLo + m0 * WSTRIDE + c + 8);
        al[3] = lds32(actLo + (m0 + 8) * WSTRIDE + c + 8);
        #pragma unroll
        for (int nt = 0; nt < 16; nt++) {
            int nr = nt * 8 + g;
            uint32_t bh[2], bl[2];
            bh[0] = lds32(wHi + nr * WSTRIDE + c);
            bh[1] = lds32(wHi + nr * WSTRIDE + c + 8);
            bl[0] = lds32(wLo + nr * WSTRIDE + c);
            bl[1] = lds32(wLo + nr * WSTRIDE + c + 8);
            mma16816(acc[nt], ah, bh);
            mma16816(acc[nt], al, bh);
            mma16816(acc[nt], ah, bl);
        }
    }
    __syncthreads();   // all warps done reading act + weights

    // ---- epilogue layer1: bias + softplus + split back to act; restage W2 ----
    #pragma unroll
    for (int nt = 0; nt < 16; nt++) {
        int n = nt * 8 + tig * 2;
        uint32_t lo, hi;
        hi = packsplit_hi(sp100f(acc[nt][0] + b1s[n]), sp100f(acc[nt][1] + b1s[n + 1]), lo);
        *(uint32_t*)(actHi + m0 * WSTRIDE + n) = hi;
        *(uint32_t*)(actLo + m0 * WSTRIDE + n) = lo;
        hi = packsplit_hi(sp100f(acc[nt][2] + b2s[0] * 0.f + b1s[n]), sp100f(acc[nt][3] + b1s[n + 1]), lo);
        *(uint32_t*)(actHi + (m0 + 8) * WSTRIDE + n) = hi;
        *(uint32_t*)(actLo + (m0 + 8) * WSTRIDE + n) = lo;
    }
    {
        const uint4* s1 = (const uint4*)&g_Wt[1][0][j][0];
        const uint4* s2 = (const uint4*)&g_Wt[1][1][j][0];
        uint4* d1 = (uint4*)wHi;
        uint4* d2 = (uint4*)wLo;
        for (int i = tid; i < (HID * WSTRIDE) / 8; i += TPB) { d1[i] = s1[i]; d2[i] = s2[i]; }
    }
    __syncthreads();

    // ================= layer 2 =================
    #pragma unroll
    for (int nt = 0; nt < 16; nt++)
        #pragma unroll
        for (int q = 0; q < 4; q++) acc[nt][q] = 0.f;

    #pragma unroll
    for (int kk = 0; kk < 8; kk++) {
        int c = kk * 16 + tig * 2;
        uint32_t ah[4], al[4];
        ah[0] = lds32(actHi + m0 * WSTRIDE + c);
        ah[1] = lds32(actHi + (m0 + 8) * WSTRIDE + c);
        ah[2] = lds32(actHi + m0 * WSTRIDE + c + 8);
        ah[3] = lds32(actHi + (m0 + 8) * WSTRIDE + c + 8);
        al[0] = lds32(actLo + m0 * WSTRIDE + c);
        al[1] = lds32(actLo + (m0 + 8) * WSTRIDE + c);
        al[2] = lds32(actLo + m0 * WSTRIDE + c + 8);
        al[3] = lds32(actLo + (m0 + 8) * WSTRIDE + c + 8);
        #pragma unroll
        for (int nt = 0; nt < 16; nt++) {
            int nr = nt * 8 + g;
            uint32_t bh[2], bl[2];
            bh[0] = lds32(wHi + nr * WSTRIDE + c);
            bh[1] = lds32(wHi + nr * WSTRIDE + c + 8);
            bl[0] = lds32(wLo + nr * WSTRIDE + c);
            bl[1] = lds32(wLo + nr * WSTRIDE + c + 8);
            mma16816(acc[nt], ah, bh);
            mma16816(acc[nt], al, bh);
            mma16816(acc[nt], ah, bl);
        }
    }

    // ---- epilogue layer2 + layer3 dot + quad reduce ----
    {
        float dot0 = 0.f, dot1 = 0.f;
        #pragma unroll
        for (int nt = 0; nt < 16; nt++) {
            int n = nt * 8 + tig * 2;
            dot0 += sp100f(acc[nt][0] + b2s[n]) * w3s[n];
            dot0 += sp100f(acc[nt][1] + b2s[n + 1]) * w3s[n + 1];
            dot1 += sp100f(acc[nt][2] + b2s[n]) * w3s[n];
            dot1 += sp100f(acc[nt][3] + b2s[n + 1]) * w3s[n + 1];
        }
        dot0 += __shfl_xor_sync(0xffffffffu, dot0, 1);
        dot0 += __shfl_xor_sync(0xffffffffu, dot0, 2);
        dot1 += __shfl_xor_sync(0xffffffffu, dot1, 1);
        dot1 += __shfl_xor_sync(0xffffffffu, dot1, 2);
        if (tig == 0) {
            float bb = b3[j];
            int va = v0 + m0;
            int vb = v0 + m0 + 8;
            if (va < NV) g_pred[j][va] = dot0 + bb;
            if (vb < NV) g_pred[j][vb] = dot1 + bb;
        }
    }
}

// ---------------------------------------------------------------------------
// Softmin blend over parts
// ---------------------------------------------------------------------------
__global__ void softmin_kernel(float* __restrict__ out) {
    int v = blockIdx.x * blockDim.x + threadIdx.x;
    if (v >= NV) return;
    float p[NJ];
    float mn = 3.0e38f;
    #pragma unroll
    for (int j = 0; j < NJ; j++) { p[j] = g_pred[j][v]; mn = fminf(mn, p[j]); }
    float se = 0.f, sd = 0.f;
    #pragma unroll
    for (int j = 0; j < NJ; j++) {
        float d = p[j] - mn;
        float e = expf(-200.0f * d);
        se += e;
        sd += d * e;
    }
    out[v] = sd / se + mn;
}

extern "C" void kernel_launch(void* const* d_in, const int* in_sizes, int n_in,
                              void* d_out, int out_size)
{
    const float* pts    = (const float*)d_in[0];
    const float* Bcond  = (const float*)d_in[1];
    const float* Btr    = (const float*)d_in[2];
    const float* Brot   = (const float*)d_in[3];
    const float* Bneigh = (const float*)d_in[4];
    const float* alpha  = (const float*)d_in[5];
    const float* beta   = (const float*)d_in[6];
    const float* cW0 = (const float*)d_in[7];
    const float* cb0 = (const float*)d_in[8];
    const float* cW1 = (const float*)d_in[9];
    const float* cb1 = (const float*)d_in[10];
    const float* cW2 = (const float*)d_in[11];
    const float* cb2 = (const float*)d_in[12];
    const float* W0  = (const float*)d_in[13];
    const float* b0  = (const float*)d_in[14];
    const float* W1  = (const float*)d_in[15];
    const float* b1  = (const float*)d_in[16];
    const float* W2  = (const float*)d_in[17];
    const float* b2  = (const float*)d_in[18];
    const float* W3  = (const float*)d_in[19];
    const float* b3  = (const float*)d_in[20];

    cudaFuncSetAttribute(main_kernel, cudaFuncAttributeMaxDynamicSharedMemorySize, SMEM_BYTES);

    pre_kernel<<<NJ, 32>>>(Bcond, Bneigh, alpha, beta, cW0, cb0, cW1, cb1, cW2, cb2);
    wconv_kernel<<<dim3(NJ, 2), 256>>>(W1, W2);

    dim3 grid((NV + MTILE - 1) / MTILE, NJ);
    main_kernel<<<grid, TPB, SMEM_BYTES>>>(pts, Btr, Brot, W0, b0, b1, b2, W3, b3);

    softmin_kernel<<<(NV + 255) / 256, 256>>>((float*)d_out);
}

// round 12
// speedup vs baseline: 1.0013x; 1.0013x over previous
#include <cuda_runtime.h>
#include <cuda_bf16.h>
#include <math.h>
#include <stdint.h>

#define NJ 24
#define NV 20000
#define NG 2
#define HID 128
#define EPSV 1e-8f
#define TPB 256
#define MTILE 128
#define WSTRIDE 136   // padded row stride (elements) for conflict-free LDS

// smem layout (bytes)
#define OFF_ACT_HI 0
#define OFF_ACT_LO 34816
#define OFF_W_HI   69632
#define OFF_W_LO   104448
#define OFF_F32    139264   // w0s[896], b0s[128], b1s[128], b2s[128], w3s[128]
#define SMEM_BYTES (139264 + (896 + 4 * 128) * 4)

__device__ float g_c[NJ][4];
__device__ float g_geom[NJ][NG][16];
__device__ float g_pred[NJ][NV];
// [layer][hi/lo][j] transposed weights Wt[n][k], stride 136, bf16
__device__ __nv_bfloat16 g_Wt[2][2][NJ][HID * WSTRIDE];

__device__ __forceinline__ float sp100(float x) {
    float t = 100.0f * x;
    if (t > 20.0f) return x;
    return log1pf(expf(t)) * 0.01f;
}
__device__ __forceinline__ float sp100f(float x) {
    return fmaxf(x, 0.0f) + __logf(1.0f + __expf(-fabsf(100.0f * x))) * 0.01f;
}
__device__ __forceinline__ float ra_elu(float x) {
    return (x - 1.0f) > 0.0f ? x : expf(x - 1.0f);
}
__device__ __forceinline__ uint32_t packsplit_hi(float a, float b, uint32_t& lo) {
    __nv_bfloat16 ha = __float2bfloat16_rn(a);
    __nv_bfloat16 hb = __float2bfloat16_rn(b);
    __nv_bfloat16 la = __float2bfloat16_rn(a - __bfloat162float(ha));
    __nv_bfloat16 lb = __float2bfloat16_rn(b - __bfloat162float(hb));
    lo = (uint32_t)__bfloat16_as_ushort(la) | ((uint32_t)__bfloat16_as_ushort(lb) << 16);
    return (uint32_t)__bfloat16_as_ushort(ha) | ((uint32_t)__bfloat16_as_ushort(hb) << 16);
}

__device__ __forceinline__ void mma16816(float* c, const uint32_t* a, const uint32_t* b) {
    asm volatile(
        "mma.sync.aligned.m16n8k16.row.col.f32.bf16.bf16.f32 "
        "{%0,%1,%2,%3}, {%4,%5,%6,%7}, {%8,%9}, {%0,%1,%2,%3};"
        : "+f"(c[0]), "+f"(c[1]), "+f"(c[2]), "+f"(c[3])
        : "r"(a[0]), "r"(a[1]), "r"(a[2]), "r"(a[3]), "r"(b[0]), "r"(b[1]));
}
__device__ __forceinline__ uint32_t lds32(const __nv_bfloat16* p) {
    return *(const uint32_t*)p;
}

// ---------------------------------------------------------------------------
// Per-part precompute (cond MLP + blending constants)
// ---------------------------------------------------------------------------
__global__ void pre_kernel(const float* __restrict__ Bcond, const float* __restrict__ Bneigh,
                           const float* __restrict__ alpha, const float* __restrict__ beta,
                           const float* __restrict__ cW0, const float* __restrict__ cb0,
                           const float* __restrict__ cW1, const float* __restrict__ cb1,
                           const float* __restrict__ cW2, const float* __restrict__ cb2)
{
    int j = blockIdx.x, lane = threadIdx.x;
    __shared__ float c0[16], c1[16];
    if (lane < 16) {
        float s = cb0[j * 16 + lane];
        const float* w = cW0 + (size_t)j * 288 * 16 + lane;
        const float* cond = Bcond + j * 288;
        for (int k = 0; k < 288; k++) s += cond[k] * w[k * 16];
        c0[lane] = sp100(s);
    }
    __syncthreads();
    if (lane < 16) {
        float s = cb1[j * 16 + lane];
        const float* w = cW1 + j * 256 + lane;
        for (int k = 0; k < 16; k++) s += c0[k] * w[k * 16];
        c1[lane] = sp100(s);
    }
    __syncthreads();
    if (lane < 4) {
        float s = cb2[j * 4 + lane];
        const float* w = cW2 + j * 64 + lane;
        for (int k = 0; k < 16; k++) s += c1[k] * w[k * 4];
        g_c[j][lane] = s;
    }
    if (lane < NG) {
        int gi = lane;
        const float* bn = Bneigh + ((j * NG + gi) * 5) * 3;
        float Jt[3] = { bn[0], bn[1], bn[2] };
        float Jc[3] = { bn[3], bn[4], bn[5] };
        float Jo[3] = { bn[6], bn[7], bn[8] };
        float Jp[3] = { bn[9], bn[10], bn[11] };
        int bt = (int)bn[12], bo = (int)bn[13];
        float a_n = ra_elu(alpha[bo * NJ + bt]);
        float a_s = ra_elu(alpha[bt * NJ + bo]);
        float be_n = beta[bo * NJ + bt];
        float be_s = beta[bt * NJ + bo];
        float nb_n = 0.f, nb_s = 0.f;
        for (int d = 0; d < 3; d++) {
            float tn = Jo[d] - Jc[d]; nb_n += tn * tn;
            float ts = Jt[d] - Jc[d]; nb_s += ts * ts;
        }
        nb_n = sqrtf(nb_n); nb_s = sqrtf(nb_s);
        float vn[3], vs[3];
        float f1 = nb_n / (nb_n + nb_s + EPSV);
        for (int d = 0; d < 3; d++) vn[d] = (Jo[d] - Jt[d]) * f1;
        float f2 = nb_s / (nb_n + EPSV);
        for (int d = 0; d < 3; d++) vs[d] = -vn[d] * f2;
        float n_n = 0.f, n_s = 0.f;
        for (int d = 0; d < 3; d++) { n_n += vn[d] * vn[d]; n_s += vs[d] * vs[d]; }
        n_n = sqrtf(n_n); n_s = sqrtf(n_s);
        float cn = a_n / ((n_n + EPSV) * (n_n + EPSV));
        float cs = a_s / ((n_s + EPSV) * (n_s + EPSV));
        float* gg = g_geom[j][gi];
        for (int d = 0; d < 3; d++) gg[d] = Jo[d] - vn[d];
        for (int d = 0; d < 3; d++) gg[3 + d] = vn[d] * cn - vs[d] * cs;
        gg[6] = be_n - be_s;
        for (int d = 0; d < 3; d++) gg[7 + d] = Jp[d];
        for (int d = 0; d < 3; d++) gg[10 + d] = Jc[d];
    }
}

// ---------------------------------------------------------------------------
// Weight conversion: fp32 W[k][n] -> bf16 hi/lo transposed Wt[n][k], stride 136
// ---------------------------------------------------------------------------
__global__ void wconv_kernel(const float* __restrict__ W1, const float* __restrict__ W2) {
    int j = blockIdx.x, layer = blockIdx.y;
    const float* W = (layer == 0 ? W1 : W2) + (size_t)j * HID * HID;
    __nv_bfloat16* dh = &g_Wt[layer][0][j][0];
    __nv_bfloat16* dl = &g_Wt[layer][1][j][0];
    for (int idx = threadIdx.x; idx < HID * WSTRIDE; idx += blockDim.x) {
        int n = idx / WSTRIDE, k = idx - n * WSTRIDE;
        if (k < HID) {
            float w = W[k * HID + n];
            __nv_bfloat16 h = __float2bfloat16_rn(w);
            __nv_bfloat16 l = __float2bfloat16_rn(w - __bfloat162float(h));
            dh[idx] = h; dl[idx] = l;
        } else {
            dh[idx] = __float2bfloat16_rn(0.f);
            dl[idx] = __float2bfloat16_rn(0.f);
        }
    }
}

// ---------------------------------------------------------------------------
// Main kernel: 128 points x 1 part per CTA, mma.sync bf16 3-pass hidden layers
// ---------------------------------------------------------------------------
__global__ __launch_bounds__(TPB, 1) void main_kernel(
    const float* __restrict__ pts, const float* __restrict__ Btr, const float* __restrict__ Brot,
    const float* __restrict__ W0, const float* __restrict__ b0,
    const float* __restrict__ b1, const float* __restrict__ b2,
    const float* __restrict__ W3, const float* __restrict__ b3)
{
    extern __shared__ char sm[];
    __nv_bfloat16* actHi = (__nv_bfloat16*)(sm + OFF_ACT_HI);
    __nv_bfloat16* actLo = (__nv_bfloat16*)(sm + OFF_ACT_LO);
    __nv_bfloat16* wHi   = (__nv_bfloat16*)(sm + OFF_W_HI);
    __nv_bfloat16* wLo   = (__nv_bfloat16*)(sm + OFF_W_LO);
    float* w0s = (float*)(sm + OFF_F32);
    float* b0s = w0s + 896;
    float* b1s = b0s + 128;
    float* b2s = b1s + 128;
    float* w3s = b2s + 128;

    int tid = threadIdx.x;
    int j = blockIdx.y;
    int v0 = blockIdx.x * MTILE;
    int w = tid >> 5, lane = tid & 31;
    int g = lane >> 2, tig = lane & 3;

    // ---- stage layer-1 weights + w0 + biases ----
    {
        const uint4* s1 = (const uint4*)&g_Wt[0][0][j][0];
        const uint4* s2 = (const uint4*)&g_Wt[0][1][j][0];
        uint4* d1 = (uint4*)wHi;
        uint4* d2 = (uint4*)wLo;
        for (int i = tid; i < (HID * WSTRIDE) / 8; i += TPB) { d1[i] = s1[i]; d2[i] = s2[i]; }
        for (int i = tid; i < 896; i += TPB) w0s[i] = W0[j * 896 + i];
        if (tid < 128) {
            b0s[tid] = b0[j * 128 + tid];
            b1s[tid] = b1[j * 128 + tid];
            b2s[tid] = b2[j * 128 + tid];
            w3s[tid] = W3[j * 128 + tid];
        }
    }

    // ---- geometry (both halves of the block compute the same row redundantly) ----
    int m = tid & (MTILE - 1);
    int half = tid >> 7;
    int v = v0 + m;
    int vc = v < NV ? v : NV - 1;
    float xk[7];
    {
        float px = pts[vc * 3 + 0] - Btr[j * 3 + 0];
        float py = pts[vc * 3 + 1] - Btr[j * 3 + 1];
        float pz = pts[vc * 3 + 2] - Btr[j * 3 + 2];
        const float* R = Brot + j * 9;
        float plx = R[0] * px + R[3] * py + R[6] * pz;
        float ply = R[1] * px + R[4] * py + R[7] * pz;
        float plz = R[2] * px + R[5] * py + R[8] * pz;
        float ox = 0.f, oy = 0.f, oz = 0.f;
        #pragma unroll
        for (int gi = 0; gi < NG; gi++) {
            const float* gg = g_geom[j][gi];
            float dx = plx - gg[0], dy = ply - gg[1], dz = plz - gg[2];
            float arg = dx * gg[3] + dy * gg[4] + dz * gg[5] + gg[6];
            float ww = 1.0f / (1.0f + expf(-arg));
            float ax = -gg[7] * ww, ay = -gg[8] * ww, az = -gg[9] * ww;
            float ang = sqrtf(ax * ax + ay * ay + az * az);
            float inv = (ang < 1e-12f) ? 1.0f : (1.0f / ang);
            float ux = ax * inv, uy = ay * inv, uz = az * inv;
            float cc = cosf(ang), ss = sinf(ang);
            float C = 1.0f - cc;
            float qx = plx - gg[10], qy = ply - gg[11], qz = plz - gg[12];
            float rx = (cc + ux * ux * C) * qx + (ux * uy * C - uz * ss) * qy + (ux * uz * C + uy * ss) * qz;
            float ry = (uy * ux * C + uz * ss) * qx + (cc + uy * uy * C) * qy + (uy * uz * C - ux * ss) * qz;
            float rz = (uz * ux * C - uy * ss) * qx + (uz * uy * C + ux * ss) * qy + (cc + uz * uz * C) * qz;
            ox += rx + gg[10] - plx;
            oy += ry + gg[11] - ply;
            oz += rz + gg[12] - plz;
        }
        xk[0] = plx + ox; xk[1] = ply + oy; xk[2] = plz + oz;
        xk[3] = g_c[j][0]; xk[4] = g_c[j][1]; xk[5] = g_c[j][2]; xk[6] = g_c[j][3];
    }
    __syncthreads();   // weights + biases staged

    // ---- layer0 (7 -> 128): each half computes 64 outputs of its row ----
    {
        int nbeg = half * 64;
        #pragma unroll
        for (int n = 0; n < 64; n += 2) {
            int nn = nbeg + n;
            float s0 = b0s[nn], s1 = b0s[nn + 1];
            #pragma unroll
            for (int k = 0; k < 7; k++) {
                s0 += xk[k] * w0s[k * 128 + nn];
                s1 += xk[k] * w0s[k * 128 + nn + 1];
            }
            uint32_t lo;
            uint32_t hi = packsplit_hi(sp100f(s0), sp100f(s1), lo);
            *(uint32_t*)(actHi + m * WSTRIDE + nn) = hi;
            *(uint32_t*)(actLo + m * WSTRIDE + nn) = lo;
        }
    }
    __syncthreads();

    int m0 = w * 16 + g;   // mma row base for this thread
    float acc[16][4];

    // ================= layer 1 =================
    #pragma unroll
    for (int nt = 0; nt < 16; nt++)
        #pragma unroll
        for (int q = 0; q < 4; q++) acc[nt][q] = 0.f;

    #pragma unroll
    for (int kk = 0; kk < 8; kk++) {
        int c = kk * 16 + tig * 2;
        uint32_t ah[4], al[4];
        ah[0] = lds32(actHi + m0 * WSTRIDE + c);
        ah[1] = lds32(actHi + (m0 + 8) * WSTRIDE + c);
        ah[2] = lds32(actHi + m0 * WSTRIDE + c + 8);
        ah[3] = lds32(actHi + (m0 + 8) * WSTRIDE + c + 8);
        al[0] = lds32(actLo + m0 * WSTRIDE + c);
        al[1] = lds32(actLo + (m0 + 8) * WSTRIDE + c);
        al[2] = lds32(actLo + m0 * WSTRIDE + c + 8);
        al[3] = lds32(actLo + (m0 + 8) * WSTRIDE + c + 8);
        #pragma unroll
        for (int nt = 0; nt < 16; nt++) {
            int nr = nt * 8 + g;
            uint32_t bh[2], bl[2];
            bh[0] = lds32(wHi + nr * WSTRIDE + c);
            bh[1] = lds32(wHi + nr * WSTRIDE + c + 8);
            bl[0] = lds32(wLo + nr * WSTRIDE + c);
            bl[1] = lds32(wLo + nr * WSTRIDE + c + 8);
            mma16816(acc[nt], ah, bh);
            mma16816(acc[nt], al, bh);
            mma16816(acc[nt], ah, bl);
        }
    }
    __syncthreads();   // all warps done reading act + weights

    // ---- epilogue layer1: bias + softplus + split back to act; restage W2 ----
    #pragma unroll
    for (int nt = 0; nt < 16; nt++) {
        int n = nt * 8 + tig * 2;
        uint32_t lo, hi;
        hi = packsplit_hi(sp100f(acc[nt][0] + b1s[n]), sp100f(acc[nt][1] + b1s[n + 1]), lo);
        *(uint32_t*)(actHi + m0 * WSTRIDE + n) = hi;
        *(uint32_t*)(actLo + m0 * WSTRIDE + n) = lo;
        hi = packsplit_hi(sp100f(acc[nt][2] + b2s[0] * 0.f + b1s[n]), sp100f(acc[nt][3] + b1s[n + 1]), lo);
        *(uint32_t*)(actHi + (m0 + 8) * WSTRIDE + n) = hi;
        *(uint32_t*)(actLo + (m0 + 8) * WSTRIDE + n) = lo;
    }
    {
        const uint4* s1 = (const uint4*)&g_Wt[1][0][j][0];
        const uint4* s2 = (const uint4*)&g_Wt[1][1][j][0];
        uint4* d1 = (uint4*)wHi;
        uint4* d2 = (uint4*)wLo;
        for (int i = tid; i < (HID * WSTRIDE) / 8; i += TPB) { d1[i] = s1[i]; d2[i] = s2[i]; }
    }
    __syncthreads();

    // ================= layer 2 =================
    #pragma unroll
    for (int nt = 0; nt < 16; nt++)
        #pragma unroll
        for (int q = 0; q < 4; q++) acc[nt][q] = 0.f;

    #pragma unroll
    for (int kk = 0; kk < 8; kk++) {
        int c = kk * 16 + tig * 2;
        uint32_t ah[4], al[4];
        ah[0] = lds32(actHi + m0 * WSTRIDE + c);
        ah[1] = lds32(actHi + (m0 + 8) * WSTRIDE + c);
        ah[2] = lds32(actHi + m0 * WSTRIDE + c + 8);
        ah[3] = lds32(actHi + (m0 + 8) * WSTRIDE + c + 8);
        al[0] = lds32(actLo + m0 * WSTRIDE + c);
        al[1] = lds32(actLo + (m0 + 8) * WSTRIDE + c);
        al[2] = lds32(actLo + m0 * WSTRIDE + c + 8);
        al[3] = lds32(actLo + (m0 + 8) * WSTRIDE + c + 8);
        #pragma unroll
        for (int nt = 0; nt < 16; nt++) {
            int nr = nt * 8 + g;
            uint32_t bh[2], bl[2];
            bh[0] = lds32(wHi + nr * WSTRIDE + c);
            bh[1] = lds32(wHi + nr * WSTRIDE + c + 8);
            bl[0] = lds32(wLo + nr * WSTRIDE + c);
            bl[1] = lds32(wLo + nr * WSTRIDE + c + 8);
            mma16816(acc[nt], ah, bh);
            mma16816(acc[nt], al, bh);
            mma16816(acc[nt], ah, bl);
        }
    }

    // ---- epilogue layer2 + layer3 dot + quad reduce ----
    {
        float dot0 = 0.f, dot1 = 0.f;
        #pragma unroll
        for (int nt = 0; nt < 16; nt++) {
            int n = nt * 8 + tig * 2;
            dot0 += sp100f(acc[nt][0] + b2s[n]) * w3s[n];
            dot0 += sp100f(acc[nt][1] + b2s[n + 1]) * w3s[n + 1];
            dot1 += sp100f(acc[nt][2] + b2s[n]) * w3s[n];
            dot1 += sp100f(acc[nt][3] + b2s[n + 1]) * w3s[n + 1];
        }
        dot0 += __shfl_xor_sync(0xffffffffu, dot0, 1);
        dot0 += __shfl_xor_sync(0xffffffffu, dot0, 2);
        dot1 += __shfl_xor_sync(0xffffffffu, dot1, 1);
        dot1 += __shfl_xor_sync(0xffffffffu, dot1, 2);
        if (tig == 0) {
            float bb = b3[j];
            int va = v0 + m0;
            int vb = v0 + m0 + 8;
            if (va < NV) g_pred[j][va] = dot0 + bb;
            if (vb < NV) g_pred[j][vb] = dot1 + bb;
        }
    }
}

// ---------------------------------------------------------------------------
// Softmin blend over parts
// ---------------------------------------------------------------------------
__global__ void softmin_kernel(float* __restrict__ out) {
    int v = blockIdx.x * blockDim.x + threadIdx.x;
    if (v >= NV) return;
    float p[NJ];
    float mn = 3.0e38f;
    #pragma unroll
    for (int j = 0; j < NJ; j++) { p[j] = g_pred[j][v]; mn = fminf(mn, p[j]); }
    float se = 0.f, sd = 0.f;
    #pragma unroll
    for (int j = 0; j < NJ; j++) {
        float d = p[j] - mn;
        float e = expf(-200.0f * d);
        se += e;
        sd += d * e;
    }
    out[v] = sd / se + mn;
}

extern "C" void kernel_launch(void* const* d_in, const int* in_sizes, int n_in,
                              void* d_out, int out_size)
{
    const float* pts    = (const float*)d_in[0];
    const float* Bcond  = (const float*)d_in[1];
    const float* Btr    = (const float*)d_in[2];
    const float* Brot   = (const float*)d_in[3];
    const float* Bneigh = (const float*)d_in[4];
    const float* alpha  = (const float*)d_in[5];
    const float* beta   = (const float*)d_in[6];
    const float* cW0 = (const float*)d_in[7];
    const float* cb0 = (const float*)d_in[8];
    const float* cW1 = (const float*)d_in[9];
    const float* cb1 = (const float*)d_in[10];
    const float* cW2 = (const float*)d_in[11];
    const float* cb2 = (const float*)d_in[12];
    const float* W0  = (const float*)d_in[13];
    const float* b0  = (const float*)d_in[14];
    const float* W1  = (const float*)d_in[15];
    const float* b1  = (const float*)d_in[16];
    const float* W2  = (const float*)d_in[17];
    const float* b2  = (const float*)d_in[18];
    const float* W3  = (const float*)d_in[19];
    const float* b3  = (const float*)d_in[20];

    cudaFuncSetAttribute(main_kernel, cudaFuncAttributeMaxDynamicSharedMemorySize, SMEM_BYTES);

    pre_kernel<<<NJ, 32>>>(Bcond, Bneigh, alpha, beta, cW0, cb0, cW1, cb1, cW2, cb2);
    wconv_kernel<<<dim3(NJ, 2), 256>>>(W1, W2);

    dim3 grid((NV + MTILE - 1) / MTILE, NJ);
    main_kernel<<<grid, TPB, SMEM_BYTES>>>(pts, Btr, Brot, W0, b0, b1, b2, W3, b3);

    softmin_kernel<<<(NV + 255) / 256, 256>>>((float*)d_out);
}

// round 13
// speedup vs baseline: 2.3916x; 2.3885x over previous
#include <cuda_runtime.h>
#include <cuda_fp16.h>
#include <cuda_bf16.h>
#include <math.h>
#include <stdint.h>

#define NJ 24
#define NV 20000
#define NG 2
#define HID 128
#define EPSV 1e-8f
#define TPB 256
#define MTILE 128

// smem: wf1[4096] uint2 (32KB) | wf2[4096] uint2 (32KB) | w0s[896] b0s/b1s/b2s/w3s[128*4] f32
#define OFF_WF1 0
#define OFF_WF2 32768
#define OFF_F32 65536
#define SMEM_BYTES (65536 + (896 + 4 * 128) * 4)

__device__ float g_c[NJ][4];
__device__ float g_geom[NJ][NG][16];
__device__ float g_pred[NJ][NV];
// fragment-major fp16 weights: [layer][j][(kk*16+nt)*32+lane] = {b0, b1}
__device__ uint2 g_Wf[2][NJ][4096];

__device__ __forceinline__ float sp100(float x) {
    float t = 100.0f * x;
    if (t > 20.0f) return x;
    return log1pf(expf(t)) * 0.01f;
}
__device__ __forceinline__ float sp100f(float x) {
    return fmaxf(x, 0.0f) + __logf(1.0f + __expf(-fabsf(100.0f * x))) * 0.01f;
}
__device__ __forceinline__ float ra_elu(float x) {
    return (x - 1.0f) > 0.0f ? x : expf(x - 1.0f);
}
__device__ __forceinline__ uint32_t f2h2(float a, float b) {
    __half2 h = __floats2half2_rn(a, b);
    return *reinterpret_cast<uint32_t*>(&h);
}
__device__ __forceinline__ void mma_f16(float* c, const uint32_t* a, uint2 b) {
    asm volatile(
        "mma.sync.aligned.m16n8k16.row.col.f32.f16.f16.f32 "
        "{%0,%1,%2,%3}, {%4,%5,%6,%7}, {%8,%9}, {%0,%1,%2,%3};"
        : "+f"(c[0]), "+f"(c[1]), "+f"(c[2]), "+f"(c[3])
        : "r"(a[0]), "r"(a[1]), "r"(a[2]), "r"(a[3]), "r"(b.x), "r"(b.y));
}

// ---------------------------------------------------------------------------
// Per-part precompute (cond MLP + blending constants)
// ---------------------------------------------------------------------------
__global__ void pre_kernel(const float* __restrict__ Bcond, const float* __restrict__ Bneigh,
                           const float* __restrict__ alpha, const float* __restrict__ beta,
                           const float* __restrict__ cW0, const float* __restrict__ cb0,
                           const float* __restrict__ cW1, const float* __restrict__ cb1,
                           const float* __restrict__ cW2, const float* __restrict__ cb2)
{
    int j = blockIdx.x, lane = threadIdx.x;
    __shared__ float c0[16], c1[16];
    if (lane < 16) {
        float s = cb0[j * 16 + lane];
        const float* w = cW0 + (size_t)j * 288 * 16 + lane;
        const float* cond = Bcond + j * 288;
        for (int k = 0; k < 288; k++) s += cond[k] * w[k * 16];
        c0[lane] = sp100(s);
    }
    __syncthreads();
    if (lane < 16) {
        float s = cb1[j * 16 + lane];
        const float* w = cW1 + j * 256 + lane;
        for (int k = 0; k < 16; k++) s += c0[k] * w[k * 16];
        c1[lane] = sp100(s);
    }
    __syncthreads();
    if (lane < 4) {
        float s = cb2[j * 4 + lane];
        const float* w = cW2 + j * 64 + lane;
        for (int k = 0; k < 16; k++) s += c1[k] * w[k * 4];
        g_c[j][lane] = s;
    }
    if (lane < NG) {
        int gi = lane;
        const float* bn = Bneigh + ((j * NG + gi) * 5) * 3;
        float Jt[3] = { bn[0], bn[1], bn[2] };
        float Jc[3] = { bn[3], bn[4], bn[5] };
        float Jo[3] = { bn[6], bn[7], bn[8] };
        float Jp[3] = { bn[9], bn[10], bn[11] };
        int bt = (int)bn[12], bo = (int)bn[13];
        float a_n = ra_elu(alpha[bo * NJ + bt]);
        float a_s = ra_elu(alpha[bt * NJ + bo]);
        float be_n = beta[bo * NJ + bt];
        float be_s = beta[bt * NJ + bo];
        float nb_n = 0.f, nb_s = 0.f;
        for (int d = 0; d < 3; d++) {
            float tn = Jo[d] - Jc[d]; nb_n += tn * tn;
            float ts = Jt[d] - Jc[d]; nb_s += ts * ts;
        }
        nb_n = sqrtf(nb_n); nb_s = sqrtf(nb_s);
        float vn[3], vs[3];
        float f1 = nb_n / (nb_n + nb_s + EPSV);
        for (int d = 0; d < 3; d++) vn[d] = (Jo[d] - Jt[d]) * f1;
        float f2 = nb_s / (nb_n + EPSV);
        for (int d = 0; d < 3; d++) vs[d] = -vn[d] * f2;
        float n_n = 0.f, n_s = 0.f;
        for (int d = 0; d < 3; d++) { n_n += vn[d] * vn[d]; n_s += vs[d] * vs[d]; }
        n_n = sqrtf(n_n); n_s = sqrtf(n_s);
        float cn = a_n / ((n_n + EPSV) * (n_n + EPSV));
        float cs = a_s / ((n_s + EPSV) * (n_s + EPSV));
        float* gg = g_geom[j][gi];
        for (int d = 0; d < 3; d++) gg[d] = Jo[d] - vn[d];
        for (int d = 0; d < 3; d++) gg[3 + d] = vn[d] * cn - vs[d] * cs;
        gg[6] = be_n - be_s;
        for (int d = 0; d < 3; d++) gg[7 + d] = Jp[d];
        for (int d = 0; d < 3; d++) gg[10 + d] = Jc[d];
    }
}

// ---------------------------------------------------------------------------
// Weight conversion: fp32 W[k][n] -> fragment-major fp16 B fragments
// fragment (kk, nt, lane): b0 = (k=c..c+1, n), b1 = (k=c+8..c+9, n)
//   n = nt*8 + lane/4,  c = kk*16 + (lane%4)*2
// ---------------------------------------------------------------------------
__global__ void wconv_kernel(const float* __restrict__ W1, const float* __restrict__ W2) {
    int j = blockIdx.x, layer = blockIdx.y;
    const float* W = (layer == 0 ? W1 : W2) + (size_t)j * HID * HID;
    for (int idx = threadIdx.x; idx < 4096; idx += blockDim.x) {
        int lane = idx & 31;
        int nt = (idx >> 5) & 15;
        int kk = idx >> 9;
        int n = nt * 8 + (lane >> 2);
        int c = kk * 16 + (lane & 3) * 2;
        uint2 b;
        b.x = f2h2(W[c * HID + n], W[(c + 1) * HID + n]);
        b.y = f2h2(W[(c + 8) * HID + n], W[(c + 9) * HID + n]);
        g_Wf[layer][j][idx] = b;
    }
}

// ---------------------------------------------------------------------------
// Main kernel: 128 points x 1 part per CTA, single-pass fp16 mma,
// fully register-resident activations (no act smem, no inter-layer syncs)
// ---------------------------------------------------------------------------
__global__ __launch_bounds__(TPB, 1) void main_kernel(
    const float* __restrict__ pts, const float* __restrict__ Btr, const float* __restrict__ Brot,
    const float* __restrict__ W0, const float* __restrict__ b0,
    const float* __restrict__ b1, const float* __restrict__ b2,
    const float* __restrict__ W3, const float* __restrict__ b3)
{
    extern __shared__ char sm[];
    uint2* wf1 = (uint2*)(sm + OFF_WF1);
    uint2* wf2 = (uint2*)(sm + OFF_WF2);
    float* w0s = (float*)(sm + OFF_F32);
    float* b0s = w0s + 896;
    float* b1s = b0s + 128;
    float* b2s = b1s + 128;
    float* w3s = b2s + 128;

    int tid = threadIdx.x;
    int j = blockIdx.y;
    int v0 = blockIdx.x * MTILE;
    int w = tid >> 5, lane = tid & 31;
    int g = lane >> 2, tig = lane & 3;

    // ---- stage both layers' fragment-major weights + w0 + biases ----
    {
        const uint4* s1 = (const uint4*)&g_Wf[0][j][0];
        const uint4* s2 = (const uint4*)&g_Wf[1][j][0];
        uint4* d1 = (uint4*)wf1;
        uint4* d2 = (uint4*)wf2;
        #pragma unroll
        for (int i = 0; i < 2048 / TPB; i++) { d1[tid + i * TPB] = s1[tid + i * TPB]; d2[tid + i * TPB] = s2[tid + i * TPB]; }
        for (int i = tid; i < 896; i += TPB) w0s[i] = W0[j * 896 + i];
        if (tid < 128) {
            b0s[tid] = b0[j * 128 + tid];
            b1s[tid] = b1[j * 128 + tid];
            b2s[tid] = b2[j * 128 + tid];
            w3s[tid] = W3[j * 128 + tid];
        }
    }

    // ---- geometry: lane L computes row (L & 15) of this warp's 16 rows ----
    int grow = lane & 15;
    int v = v0 + w * 16 + grow;
    int vc = v < NV ? v : NV - 1;
    float xk[7];
    {
        float px = pts[vc * 3 + 0] - Btr[j * 3 + 0];
        float py = pts[vc * 3 + 1] - Btr[j * 3 + 1];
        float pz = pts[vc * 3 + 2] - Btr[j * 3 + 2];
        const float* R = Brot + j * 9;
        float plx = R[0] * px + R[3] * py + R[6] * pz;
        float ply = R[1] * px + R[4] * py + R[7] * pz;
        float plz = R[2] * px + R[5] * py + R[8] * pz;
        float ox = 0.f, oy = 0.f, oz = 0.f;
        #pragma unroll
        for (int gi = 0; gi < NG; gi++) {
            const float* gg = g_geom[j][gi];
            float dx = plx - gg[0], dy = ply - gg[1], dz = plz - gg[2];
            float arg = dx * gg[3] + dy * gg[4] + dz * gg[5] + gg[6];
            float ww = 1.0f / (1.0f + expf(-arg));
            float ax = -gg[7] * ww, ay = -gg[8] * ww, az = -gg[9] * ww;
            float ang = sqrtf(ax * ax + ay * ay + az * az);
            float inv = (ang < 1e-12f) ? 1.0f : (1.0f / ang);
            float ux = ax * inv, uy = ay * inv, uz = az * inv;
            float cc = cosf(ang), ss = sinf(ang);
            float C = 1.0f - cc;
            float qx = plx - gg[10], qy = ply - gg[11], qz = plz - gg[12];
            float rx = (cc + ux * ux * C) * qx + (ux * uy * C - uz * ss) * qy + (ux * uz * C + uy * ss) * qz;
            float ry = (uy * ux * C + uz * ss) * qx + (cc + uy * uy * C) * qy + (uy * uz * C - ux * ss) * qz;
            float rz = (uz * ux * C - uy * ss) * qx + (uz * uy * C + ux * ss) * qy + (cc + uz * uz * C) * qz;
            ox += rx + gg[10] - plx;
            oy += ry + gg[11] - ply;
            oz += rz + gg[12] - plz;
        }
        xk[0] = plx + ox; xk[1] = ply + oy; xk[2] = plz + oz;
        xk[3] = g_c[j][0]; xk[4] = g_c[j][1]; xk[5] = g_c[j][2]; xk[6] = g_c[j][3];
    }

    // redistribute xk: this thread owns rows g and g+8
    float xka[7], xkb[7];
    #pragma unroll
    for (int k = 0; k < 7; k++) {
        xka[k] = __shfl_sync(0xffffffffu, xk[k], g);
        xkb[k] = __shfl_sync(0xffffffffu, xk[k], g + 8);
    }
    __syncthreads();   // weights + biases staged

    // ---- layer0 (7 -> 128) directly into A fragments (registers) ----
    uint32_t frag[8][4];
    #pragma unroll
    for (int kk = 0; kk < 8; kk++) {
        int c = kk * 16 + tig * 2;
        int cols[4] = { c, c + 1, c + 8, c + 9 };
        float sa[4], sb[4];
        #pragma unroll
        for (int ci = 0; ci < 4; ci++) { sa[ci] = b0s[cols[ci]]; sb[ci] = sa[ci]; }
        #pragma unroll
        for (int k = 0; k < 7; k++) {
            #pragma unroll
            for (int ci = 0; ci < 4; ci++) {
                float wv = w0s[k * 128 + cols[ci]];
                sa[ci] += xka[k] * wv;
                sb[ci] += xkb[k] * wv;
            }
        }
        frag[kk][0] = f2h2(sp100f(sa[0]), sp100f(sa[1]));
        frag[kk][1] = f2h2(sp100f(sb[0]), sp100f(sb[1]));
        frag[kk][2] = f2h2(sp100f(sa[2]), sp100f(sa[3]));
        frag[kk][3] = f2h2(sp100f(sb[2]), sp100f(sb[3]));
    }

    // ================= layer 1 =================
    float acc[16][4];
    #pragma unroll
    for (int nt = 0; nt < 16; nt++)
        #pragma unroll
        for (int q = 0; q < 4; q++) acc[nt][q] = 0.f;

    #pragma unroll
    for (int kk = 0; kk < 8; kk++) {
        const uint2* wrow = wf1 + kk * 512 + lane;
        #pragma unroll
        for (int nt = 0; nt < 16; nt++) {
            uint2 b = wrow[nt * 32];
            mma_f16(acc[nt], frag[kk], b);
        }
    }

    // ---- epilogue layer1: bias + softplus -> layer-2 A fragments (registers) ----
    #pragma unroll
    for (int kk = 0; kk < 8; kk++) {
        int n0 = kk * 16 + tig * 2;
        int n1 = n0 + 8;
        frag[kk][0] = f2h2(sp100f(acc[2 * kk][0] + b1s[n0]), sp100f(acc[2 * kk][1] + b1s[n0 + 1]));
        frag[kk][1] = f2h2(sp100f(acc[2 * kk][2] + b1s[n0]), sp100f(acc[2 * kk][3] + b1s[n0 + 1]));
        frag[kk][2] = f2h2(sp100f(acc[2 * kk + 1][0] + b1s[n1]), sp100f(acc[2 * kk + 1][1] + b1s[n1 + 1]));
        frag[kk][3] = f2h2(sp100f(acc[2 * kk + 1][2] + b1s[n1]), sp100f(acc[2 * kk + 1][3] + b1s[n1 + 1]));
    }

    // ================= layer 2 =================
    #pragma unroll
    for (int nt = 0; nt < 16; nt++)
        #pragma unroll
        for (int q = 0; q < 4; q++) acc[nt][q] = 0.f;

    #pragma unroll
    for (int kk = 0; kk < 8; kk++) {
        const uint2* wrow = wf2 + kk * 512 + lane;
        #pragma unroll
        for (int nt = 0; nt < 16; nt++) {
            uint2 b = wrow[nt * 32];
            mma_f16(acc[nt], frag[kk], b);
        }
    }

    // ---- epilogue layer2 + layer3 dot + quad reduce ----
    {
        float dot0 = 0.f, dot1 = 0.f;
        #pragma unroll
        for (int nt = 0; nt < 16; nt++) {
            int n = nt * 8 + tig * 2;
            dot0 += sp100f(acc[nt][0] + b2s[n]) * w3s[n];
            dot0 += sp100f(acc[nt][1] + b2s[n + 1]) * w3s[n + 1];
            dot1 += sp100f(acc[nt][2] + b2s[n]) * w3s[n];
            dot1 += sp100f(acc[nt][3] + b2s[n + 1]) * w3s[n + 1];
        }
        dot0 += __shfl_xor_sync(0xffffffffu, dot0, 1);
        dot0 += __shfl_xor_sync(0xffffffffu, dot0, 2);
        dot1 += __shfl_xor_sync(0xffffffffu, dot1, 1);
        dot1 += __shfl_xor_sync(0xffffffffu, dot1, 2);
        if (tig == 0) {
            float bb = b3[j];
            int m0 = w * 16 + g;
            int va = v0 + m0;
            int vb = v0 + m0 + 8;
            if (va < NV) g_pred[j][va] = dot0 + bb;
            if (vb < NV) g_pred[j][vb] = dot1 + bb;
        }
    }
}

// ---------------------------------------------------------------------------
// Softmin blend over parts
// ---------------------------------------------------------------------------
__global__ void softmin_kernel(float* __restrict__ out) {
    int v = blockIdx.x * blockDim.x + threadIdx.x;
    if (v >= NV) return;
    float p[NJ];
    float mn = 3.0e38f;
    #pragma unroll
    for (int j = 0; j < NJ; j++) { p[j] = g_pred[j][v]; mn = fminf(mn, p[j]); }
    float se = 0.f, sd = 0.f;
    #pragma unroll
    for (int j = 0; j < NJ; j++) {
        float d = p[j] - mn;
        float e = expf(-200.0f * d);
        se += e;
        sd += d * e;
    }
    out[v] = sd / se + mn;
}

extern "C" void kernel_launch(void* const* d_in, const int* in_sizes, int n_in,
                              void* d_out, int out_size)
{
    const float* pts    = (const float*)d_in[0];
    const float* Bcond  = (const float*)d_in[1];
    const float* Btr    = (const float*)d_in[2];
    const float* Brot   = (const float*)d_in[3];
    const float* Bneigh = (const float*)d_in[4];
    const float* alpha  = (const float*)d_in[5];
    const float* beta   = (const float*)d_in[6];
    const float* cW0 = (const float*)d_in[7];
    const float* cb0 = (const float*)d_in[8];
    const float* cW1 = (const float*)d_in[9];
    const float* cb1 = (const float*)d_in[10];
    const float* cW2 = (const float*)d_in[11];
    const float* cb2 = (const float*)d_in[12];
    const float* W0  = (const float*)d_in[13];
    const float* b0  = (const float*)d_in[14];
    const float* W1  = (const float*)d_in[15];
    const float* b1  = (const float*)d_in[16];
    const float* W2  = (const float*)d_in[17];
    const float* b2  = (const float*)d_in[18];
    const float* W3  = (const float*)d_in[19];
    const float* b3  = (const float*)d_in[20];

    cudaFuncSetAttribute(main_kernel, cudaFuncAttributeMaxDynamicSharedMemorySize, SMEM_BYTES);

    pre_kernel<<<NJ, 32>>>(Bcond, Bneigh, alpha, beta, cW0, cb0, cW1, cb1, cW2, cb2);
    wconv_kernel<<<dim3(NJ, 2), 256>>>(W1, W2);

    dim3 grid((NV + MTILE - 1) / MTILE, NJ);
    main_kernel<<<grid, TPB, SMEM_BYTES>>>(pts, Btr, Brot, W0, b0, b1, b2, W3, b3);

    softmin_kernel<<<(NV + 255) / 256, 256>>>((float*)d_out);
}

// round 14
// speedup vs baseline: 2.8966x; 1.2112x over previous
#include <cuda_runtime.h>
#include <cuda_fp16.h>
#include <math.h>
#include <stdint.h>

#define NJ 24
#define NV 20000
#define NG 2
#define HID 128
#define EPSV 1e-8f
#define TPB 256
#define MTILE 128

// main smem: wf[4096] uint4 (64KB: layer1 0..2047, layer2 2048..4095) | f32 tail
#define OFF_F32 65536
#define SMEM_MAIN (65536 + (896 + 4 * 128) * 4)
#define SMEM_SETUP 65536

__device__ float g_c[NJ][4];
__device__ float g_geom[NJ][NG][16];
__device__ float g_pred[NJ][NV];
// fragment-major fp16 weights, nt-paired: [layer][j][(kk*8+ntp)*32+lane] =
//   {b(nt=2ntp).x, b(nt=2ntp).y, b(nt=2ntp+1).x, b(nt=2ntp+1).y}
__device__ uint4 g_Wf4[2][NJ][2048];

__device__ __forceinline__ float sp100(float x) {
    float t = 100.0f * x;
    if (t > 20.0f) return x;
    return log1pf(expf(t)) * 0.01f;
}
__device__ __forceinline__ float sp100f(float x) {
    return fmaxf(x, 0.0f) + __logf(1.0f + __expf(-fabsf(100.0f * x))) * 0.01f;
}
__device__ __forceinline__ float ra_elu(float x) {
    return (x - 1.0f) > 0.0f ? x : expf(x - 1.0f);
}
__device__ __forceinline__ uint32_t f2h2(float a, float b) {
    __half2 h = __floats2half2_rn(a, b);
    return *reinterpret_cast<uint32_t*>(&h);
}
__device__ __forceinline__ void mma_f16(float* c, const uint32_t* a, uint32_t b0, uint32_t b1) {
    asm volatile(
        "mma.sync.aligned.m16n8k16.row.col.f32.f16.f16.f32 "
        "{%0,%1,%2,%3}, {%4,%5,%6,%7}, {%8,%9}, {%0,%1,%2,%3};"
        : "+f"(c[0]), "+f"(c[1]), "+f"(c[2]), "+f"(c[3])
        : "r"(a[0]), "r"(a[1]), "r"(a[2]), "r"(a[3]), "r"(b0), "r"(b1));
}

// ---------------------------------------------------------------------------
// Setup kernel: blocks 0..47 = weight conversion (j = b>>1, layer = b&1),
// block 48 = per-part precompute (cond MLP + blending constants), warp-parallel
// ---------------------------------------------------------------------------
__global__ __launch_bounds__(256, 1) void setup_kernel(
    const float* __restrict__ W1, const float* __restrict__ W2,
    const float* __restrict__ Bcond, const float* __restrict__ Bneigh,
    const float* __restrict__ alpha, const float* __restrict__ beta,
    const float* __restrict__ cW0, const float* __restrict__ cb0,
    const float* __restrict__ cW1, const float* __restrict__ cb1,
    const float* __restrict__ cW2, const float* __restrict__ cb2)
{
    extern __shared__ float Wsm[];   // 16384 floats (64KB) for wconv blocks
    int tid = threadIdx.x;
    int b = blockIdx.x;

    if (b < 2 * NJ) {
        // ---- weight conversion ----
        int j = b >> 1, layer = b & 1;
        const float* W = (layer == 0 ? W1 : W2) + (size_t)j * HID * HID;
        const float4* src = (const float4*)W;
        float4* dst = (float4*)Wsm;
        #pragma unroll
        for (int i = 0; i < 16; i++) dst[tid + i * 256] = src[tid + i * 256];
        __syncthreads();
        #pragma unroll
        for (int i = 0; i < 8; i++) {
            int idx4 = tid + i * 256;
            int lane = idx4 & 31;
            int ntp  = (idx4 >> 5) & 7;
            int kk   = idx4 >> 8;
            int ne = ntp * 16 + (lane >> 2);
            int no = ne + 8;
            int c  = kk * 16 + (lane & 3) * 2;
            uint4 bb;
            bb.x = f2h2(Wsm[c * HID + ne], Wsm[(c + 1) * HID + ne]);
            bb.y = f2h2(Wsm[(c + 8) * HID + ne], Wsm[(c + 9) * HID + ne]);
            bb.z = f2h2(Wsm[c * HID + no], Wsm[(c + 1) * HID + no]);
            bb.w = f2h2(Wsm[(c + 8) * HID + no], Wsm[(c + 9) * HID + no]);
            g_Wf4[layer][j][idx4] = bb;
        }
        return;
    }

    // ---- precompute: 8 warps, each handles j = warp, warp+8, warp+16 ----
    int w = tid >> 5, lane = tid & 31;
    int o16 = lane & 15;
    int halfk = lane >> 4;
    for (int j = w; j < NJ; j += 8) {
        // cond layer0: 288 -> 16 (k split across 2 half-warps, shfl reduce)
        float s = 0.f;
        {
            const float* wp = cW0 + (size_t)j * 288 * 16 + o16;
            const float* cond = Bcond + j * 288;
            int k0 = halfk * 144;
            #pragma unroll 4
            for (int k = k0; k < k0 + 144; k++) s += cond[k] * wp[k * 16];
        }
        s += __shfl_xor_sync(0xffffffffu, s, 16);
        s += cb0[j * 16 + o16];
        float c0v = sp100(s);
        // cond layer1: 16 -> 16
        float t = cb1[j * 16 + o16];
        #pragma unroll
        for (int k = 0; k < 16; k++)
            t += __shfl_sync(0xffffffffu, c0v, k) * cW1[j * 256 + k * 16 + o16];
        float c1v = sp100(t);
        // cond layer2: 16 -> 4
        int o4 = lane & 3;
        float u = cb2[j * 4 + o4];
        #pragma unroll
        for (int k = 0; k < 16; k++)
            u += __shfl_sync(0xffffffffu, c1v, k) * cW2[j * 64 + k * 4 + o4];
        if (lane < 4) g_c[j][lane] = u;

        // blending constants (lanes 0,1)
        if (lane < NG) {
            int gi = lane;
            const float* bn = Bneigh + ((j * NG + gi) * 5) * 3;
            float Jt[3] = { bn[0], bn[1], bn[2] };
            float Jc[3] = { bn[3], bn[4], bn[5] };
            float Jo[3] = { bn[6], bn[7], bn[8] };
            float Jp[3] = { bn[9], bn[10], bn[11] };
            int bt = (int)bn[12], bo = (int)bn[13];
            float a_n = ra_elu(alpha[bo * NJ + bt]);
            float a_s = ra_elu(alpha[bt * NJ + bo]);
            float be_n = beta[bo * NJ + bt];
            float be_s = beta[bt * NJ + bo];
            float nb_n = 0.f, nb_s = 0.f;
            for (int d = 0; d < 3; d++) {
                float tn = Jo[d] - Jc[d]; nb_n += tn * tn;
                float ts = Jt[d] - Jc[d]; nb_s += ts * ts;
            }
            nb_n = sqrtf(nb_n); nb_s = sqrtf(nb_s);
            float vn[3], vs[3];
            float f1 = nb_n / (nb_n + nb_s + EPSV);
            for (int d = 0; d < 3; d++) vn[d] = (Jo[d] - Jt[d]) * f1;
            float f2 = nb_s / (nb_n + EPSV);
            for (int d = 0; d < 3; d++) vs[d] = -vn[d] * f2;
            float n_n = 0.f, n_s = 0.f;
            for (int d = 0; d < 3; d++) { n_n += vn[d] * vn[d]; n_s += vs[d] * vs[d]; }
            n_n = sqrtf(n_n); n_s = sqrtf(n_s);
            float cn = a_n / ((n_n + EPSV) * (n_n + EPSV));
            float cs = a_s / ((n_s + EPSV) * (n_s + EPSV));
            float* gg = g_geom[j][gi];
            for (int d = 0; d < 3; d++) gg[d] = Jo[d] - vn[d];
            for (int d = 0; d < 3; d++) gg[3 + d] = vn[d] * cn - vs[d] * cs;
            gg[6] = be_n - be_s;
            for (int d = 0; d < 3; d++) gg[7 + d] = Jp[d];
            for (int d = 0; d < 3; d++) gg[10 + d] = Jc[d];
        }
    }
}

// ---------------------------------------------------------------------------
// Main kernel: 128 points x 1 part per CTA, single-pass fp16 mma,
// register-resident activations, 2 CTAs/SM
// ---------------------------------------------------------------------------
__global__ __launch_bounds__(TPB, 2) void main_kernel(
    const float* __restrict__ pts, const float* __restrict__ Btr, const float* __restrict__ Brot,
    const float* __restrict__ W0, const float* __restrict__ b0,
    const float* __restrict__ b1, const float* __restrict__ b2,
    const float* __restrict__ W3, const float* __restrict__ b3)
{
    extern __shared__ char sm[];
    uint4* wf = (uint4*)sm;                 // [0..2047]=layer1, [2048..4095]=layer2
    float* w0s = (float*)(sm + OFF_F32);
    float* b0s = w0s + 896;
    float* b1s = b0s + 128;
    float* b2s = b1s + 128;
    float* w3s = b2s + 128;

    int tid = threadIdx.x;
    int j = blockIdx.y;
    int v0 = blockIdx.x * MTILE;
    int w = tid >> 5, lane = tid & 31;
    int g = lane >> 2, tig = lane & 3;

    // ---- stage both layers' fragments + w0 + biases ----
    {
        const uint4* s1 = &g_Wf4[0][j][0];
        const uint4* s2 = &g_Wf4[1][j][0];
        #pragma unroll
        for (int i = 0; i < 8; i++) {
            wf[tid + i * TPB] = s1[tid + i * TPB];
            wf[2048 + tid + i * TPB] = s2[tid + i * TPB];
        }
        for (int i = tid; i < 896; i += TPB) w0s[i] = W0[j * 896 + i];
        if (tid < 128) {
            b0s[tid] = b0[j * 128 + tid];
            b1s[tid] = b1[j * 128 + tid];
            b2s[tid] = b2[j * 128 + tid];
            w3s[tid] = W3[j * 128 + tid];
        }
    }

    // ---- geometry: lane L computes row (L & 15) of this warp's 16 rows ----
    int grow = lane & 15;
    int v = v0 + w * 16 + grow;
    int vc = v < NV ? v : NV - 1;
    float xk[7];
    {
        float px = pts[vc * 3 + 0] - Btr[j * 3 + 0];
        float py = pts[vc * 3 + 1] - Btr[j * 3 + 1];
        float pz = pts[vc * 3 + 2] - Btr[j * 3 + 2];
        const float* R = Brot + j * 9;
        float plx = R[0] * px + R[3] * py + R[6] * pz;
        float ply = R[1] * px + R[4] * py + R[7] * pz;
        float plz = R[2] * px + R[5] * py + R[8] * pz;
        float ox = 0.f, oy = 0.f, oz = 0.f;
        #pragma unroll
        for (int gi = 0; gi < NG; gi++) {
            const float* gg = g_geom[j][gi];
            float dx = plx - gg[0], dy = ply - gg[1], dz = plz - gg[2];
            float arg = dx * gg[3] + dy * gg[4] + dz * gg[5] + gg[6];
            float ww = 1.0f / (1.0f + expf(-arg));
            float ax = -gg[7] * ww, ay = -gg[8] * ww, az = -gg[9] * ww;
            float ang = sqrtf(ax * ax + ay * ay + az * az);
            float inv = (ang < 1e-12f) ? 1.0f : (1.0f / ang);
            float ux = ax * inv, uy = ay * inv, uz = az * inv;
            float cc = cosf(ang), ss = sinf(ang);
            float C = 1.0f - cc;
            float qx = plx - gg[10], qy = ply - gg[11], qz = plz - gg[12];
            float rx = (cc + ux * ux * C) * qx + (ux * uy * C - uz * ss) * qy + (ux * uz * C + uy * ss) * qz;
            float ry = (uy * ux * C + uz * ss) * qx + (cc + uy * uy * C) * qy + (uy * uz * C - ux * ss) * qz;
            float rz = (uz * ux * C - uy * ss) * qx + (uz * uy * C + ux * ss) * qy + (cc + uz * uz * C) * qz;
            ox += rx + gg[10] - plx;
            oy += ry + gg[11] - ply;
            oz += rz + gg[12] - plz;
        }
        xk[0] = plx + ox; xk[1] = ply + oy; xk[2] = plz + oz;
        xk[3] = g_c[j][0]; xk[4] = g_c[j][1]; xk[5] = g_c[j][2]; xk[6] = g_c[j][3];
    }

    // redistribute xk: this thread owns rows g and g+8
    float xka[7], xkb[7];
    #pragma unroll
    for (int k = 0; k < 7; k++) {
        xka[k] = __shfl_sync(0xffffffffu, xk[k], g);
        xkb[k] = __shfl_sync(0xffffffffu, xk[k], g + 8);
    }
    __syncthreads();   // weights + biases staged

    // ---- layer0 (7 -> 128) directly into A fragments (registers) ----
    uint32_t frag[8][4];
    #pragma unroll
    for (int kk = 0; kk < 8; kk++) {
        int c = kk * 16 + tig * 2;
        int cols[4] = { c, c + 1, c + 8, c + 9 };
        float sa[4], sb[4];
        #pragma unroll
        for (int ci = 0; ci < 4; ci++) { sa[ci] = b0s[cols[ci]]; sb[ci] = sa[ci]; }
        #pragma unroll
        for (int k = 0; k < 7; k++) {
            #pragma unroll
            for (int ci = 0; ci < 4; ci++) {
                float wv = w0s[k * 128 + cols[ci]];
                sa[ci] += xka[k] * wv;
                sb[ci] += xkb[k] * wv;
            }
        }
        frag[kk][0] = f2h2(sp100f(sa[0]), sp100f(sa[1]));
        frag[kk][1] = f2h2(sp100f(sb[0]), sp100f(sb[1]));
        frag[kk][2] = f2h2(sp100f(sa[2]), sp100f(sa[3]));
        frag[kk][3] = f2h2(sp100f(sb[2]), sp100f(sb[3]));
    }

    // ================= layer 1 =================
    float acc[16][4];
    #pragma unroll
    for (int nt = 0; nt < 16; nt++)
        #pragma unroll
        for (int q = 0; q < 4; q++) acc[nt][q] = 0.f;

    #pragma unroll
    for (int kk = 0; kk < 8; kk++) {
        const uint4* wrow = wf + kk * 256 + lane;
        #pragma unroll
        for (int ntp = 0; ntp < 8; ntp++) {
            uint4 bb = wrow[ntp * 32];
            mma_f16(acc[2 * ntp],     frag[kk], bb.x, bb.y);
            mma_f16(acc[2 * ntp + 1], frag[kk], bb.z, bb.w);
        }
    }

    // ---- epilogue layer1: bias + softplus -> layer-2 A fragments ----
    #pragma unroll
    for (int kk = 0; kk < 8; kk++) {
        int n0 = kk * 16 + tig * 2;
        int n1 = n0 + 8;
        frag[kk][0] = f2h2(sp100f(acc[2 * kk][0] + b1s[n0]), sp100f(acc[2 * kk][1] + b1s[n0 + 1]));
        frag[kk][1] = f2h2(sp100f(acc[2 * kk][2] + b1s[n0]), sp100f(acc[2 * kk][3] + b1s[n0 + 1]));
        frag[kk][2] = f2h2(sp100f(acc[2 * kk + 1][0] + b1s[n1]), sp100f(acc[2 * kk + 1][1] + b1s[n1 + 1]));
        frag[kk][3] = f2h2(sp100f(acc[2 * kk + 1][2] + b1s[n1]), sp100f(acc[2 * kk + 1][3] + b1s[n1 + 1]));
    }

    // ================= layer 2 =================
    #pragma unroll
    for (int nt = 0; nt < 16; nt++)
        #pragma unroll
        for (int q = 0; q < 4; q++) acc[nt][q] = 0.f;

    #pragma unroll
    for (int kk = 0; kk < 8; kk++) {
        const uint4* wrow = wf + 2048 + kk * 256 + lane;
        #pragma unroll
        for (int ntp = 0; ntp < 8; ntp++) {
            uint4 bb = wrow[ntp * 32];
            mma_f16(acc[2 * ntp],     frag[kk], bb.x, bb.y);
            mma_f16(acc[2 * ntp + 1], frag[kk], bb.z, bb.w);
        }
    }

    // ---- epilogue layer2 + layer3 dot + quad reduce ----
    {
        float dot0 = 0.f, dot1 = 0.f;
        #pragma unroll
        for (int nt = 0; nt < 16; nt++) {
            int n = nt * 8 + tig * 2;
            dot0 += sp100f(acc[nt][0] + b2s[n]) * w3s[n];
            dot0 += sp100f(acc[nt][1] + b2s[n + 1]) * w3s[n + 1];
            dot1 += sp100f(acc[nt][2] + b2s[n]) * w3s[n];
            dot1 += sp100f(acc[nt][3] + b2s[n + 1]) * w3s[n + 1];
        }
        dot0 += __shfl_xor_sync(0xffffffffu, dot0, 1);
        dot0 += __shfl_xor_sync(0xffffffffu, dot0, 2);
        dot1 += __shfl_xor_sync(0xffffffffu, dot1, 1);
        dot1 += __shfl_xor_sync(0xffffffffu, dot1, 2);
        if (tig == 0) {
            float bb = b3[j];
            int m0 = w * 16 + g;
            int va = v0 + m0;
            int vb = v0 + m0 + 8;
            if (va < NV) g_pred[j][va] = dot0 + bb;
            if (vb < NV) g_pred[j][vb] = dot1 + bb;
        }
    }
}

// ---------------------------------------------------------------------------
// Softmin blend over parts
// ---------------------------------------------------------------------------
__global__ void softmin_kernel(float* __restrict__ out) {
    int v = blockIdx.x * blockDim.x + threadIdx.x;
    if (v >= NV) return;
    float p[NJ];
    float mn = 3.0e38f;
    #pragma unroll
    for (int j = 0; j < NJ; j++) { p[j] = g_pred[j][v]; mn = fminf(mn, p[j]); }
    float se = 0.f, sd = 0.f;
    #pragma unroll
    for (int j = 0; j < NJ; j++) {
        float d = p[j] - mn;
        float e = expf(-200.0f * d);
        se += e;
        sd += d * e;
    }
    out[v] = sd / se + mn;
}

extern "C" void kernel_launch(void* const* d_in, const int* in_sizes, int n_in,
                              void* d_out, int out_size)
{
    const float* pts    = (const float*)d_in[0];
    const float* Bcond  = (const float*)d_in[1];
    const float* Btr    = (const float*)d_in[2];
    const float* Brot   = (const float*)d_in[3];
    const float* Bneigh = (const float*)d_in[4];
    const float* alpha  = (const float*)d_in[5];
    const float* beta   = (const float*)d_in[6];
    const float* cW0 = (const float*)d_in[7];
    const float* cb0 = (const float*)d_in[8];
    const float* cW1 = (const float*)d_in[9];
    const float* cb1 = (const float*)d_in[10];
    const float* cW2 = (const float*)d_in[11];
    const float* cb2 = (const float*)d_in[12];
    const float* W0  = (const float*)d_in[13];
    const float* b0  = (const float*)d_in[14];
    const float* W1  = (const float*)d_in[15];
    const float* b1  = (const float*)d_in[16];
    const float* W2  = (const float*)d_in[17];
    const float* b2  = (const float*)d_in[18];
    const float* W3  = (const float*)d_in[19];
    const float* b3  = (const float*)d_in[20];

    cudaFuncSetAttribute(setup_kernel, cudaFuncAttributeMaxDynamicSharedMemorySize, SMEM_SETUP);
    cudaFuncSetAttribute(main_kernel, cudaFuncAttributeMaxDynamicSharedMemorySize, SMEM_MAIN);

    setup_kernel<<<2 * NJ + 1, 256, SMEM_SETUP>>>(W1, W2, Bcond, Bneigh, alpha, beta,
                                                  cW0, cb0, cW1, cb1, cW2, cb2);

    dim3 grid((NV + MTILE - 1) / MTILE, NJ);
    main_kernel<<<grid, TPB, SMEM_MAIN>>>(pts, Btr, Brot, W0, b0, b1, b2, W3, b3);

    softmin_kernel<<<(NV + 255) / 256, 256>>>((float*)d_out);
}

// round 15
// speedup vs baseline: 3.2156x; 1.1101x over previous
#include <cuda_runtime.h>
#include <cuda_fp16.h>
#include <math.h>
#include <stdint.h>

#define NJ 24
#define NV 20000
#define NG 2
#define HID 128
#define EPSV 1e-8f
#define TPB 256
#define MTILE 128

// main smem: wf[4096] uint4 (64KB: layer1 0..2047, layer2 2048..4095) | f32 tail
#define OFF_F32 65536
#define SMEM_MAIN (65536 + (896 + 4 * 128) * 4)
#define SMEM_SETUP 65536

__device__ float g_c[NJ][4];
__device__ float g_geom[NJ][NG][16];
__device__ float g_pred[NJ][NV];
// fragment-major fp16 weights, nt-paired: [layer][j][(kk*8+ntp)*32+lane] =
//   {b(nt=2ntp).x, b(nt=2ntp).y, b(nt=2ntp+1).x, b(nt=2ntp+1).y}
__device__ uint4 g_Wf4[2][NJ][2048];

__device__ __forceinline__ float sp100(float x) {
    float t = 100.0f * x;
    if (t > 20.0f) return x;
    return log1pf(expf(t)) * 0.01f;
}
__device__ __forceinline__ float sp100f(float x) {
    return fmaxf(x, 0.0f) + __logf(1.0f + __expf(-fabsf(100.0f * x))) * 0.01f;
}
__device__ __forceinline__ float ra_elu(float x) {
    return (x - 1.0f) > 0.0f ? x : expf(x - 1.0f);
}
__device__ __forceinline__ uint32_t f2h2(float a, float b) {
    __half2 h = __floats2half2_rn(a, b);
    return *reinterpret_cast<uint32_t*>(&h);
}
__device__ __forceinline__ void mma_f16(float* c, const uint32_t* a, uint32_t b0, uint32_t b1) {
    asm volatile(
        "mma.sync.aligned.m16n8k16.row.col.f32.f16.f16.f32 "
        "{%0,%1,%2,%3}, {%4,%5,%6,%7}, {%8,%9}, {%0,%1,%2,%3};"
        : "+f"(c[0]), "+f"(c[1]), "+f"(c[2]), "+f"(c[3])
        : "r"(a[0]), "r"(a[1]), "r"(a[2]), "r"(a[3]), "r"(b0), "r"(b1));
}

// ---------------------------------------------------------------------------
// Setup kernel: blocks 0..47 = weight conversion (j = b>>1, layer = b&1),
// blocks 48..71 = per-part precompute, one part per block, block-parallel GEMV
// ---------------------------------------------------------------------------
__global__ __launch_bounds__(256, 1) void setup_kernel(
    const float* __restrict__ W1, const float* __restrict__ W2,
    const float* __restrict__ Bcond, const float* __restrict__ Bneigh,
    const float* __restrict__ alpha, const float* __restrict__ beta,
    const float* __restrict__ cW0, const float* __restrict__ cb0,
    const float* __restrict__ cW1, const float* __restrict__ cb1,
    const float* __restrict__ cW2, const float* __restrict__ cb2)
{
    extern __shared__ float Wsm[];   // 16384 floats (64KB) for wconv blocks
    int tid = threadIdx.x;
    int b = blockIdx.x;

    if (b < 2 * NJ) {
        // ---- weight conversion ----
        int j = b >> 1, layer = b & 1;
        const float* W = (layer == 0 ? W1 : W2) + (size_t)j * HID * HID;
        const float4* src = (const float4*)W;
        float4* dst = (float4*)Wsm;
        #pragma unroll
        for (int i = 0; i < 16; i++) dst[tid + i * 256] = src[tid + i * 256];
        __syncthreads();
        #pragma unroll
        for (int i = 0; i < 8; i++) {
            int idx4 = tid + i * 256;
            int lane = idx4 & 31;
            int ntp  = (idx4 >> 5) & 7;
            int kk   = idx4 >> 8;
            int ne = ntp * 16 + (lane >> 2);
            int no = ne + 8;
            int c  = kk * 16 + (lane & 3) * 2;
            uint4 bb;
            bb.x = f2h2(Wsm[c * HID + ne], Wsm[(c + 1) * HID + ne]);
            bb.y = f2h2(Wsm[(c + 8) * HID + ne], Wsm[(c + 9) * HID + ne]);
            bb.z = f2h2(Wsm[c * HID + no], Wsm[(c + 1) * HID + no]);
            bb.w = f2h2(Wsm[(c + 8) * HID + no], Wsm[(c + 9) * HID + no]);
            g_Wf4[layer][j][idx4] = bb;
        }
        return;
    }

    // ---- per-part precompute: one j per block, 256-thread GEMV ----
    int j = b - 2 * NJ;
    float* partial = Wsm;            // [16][16] partial sums
    float* c0s = Wsm + 256;          // [16]
    float* c1s = Wsm + 272;          // [16]

    {
        // cond layer0: 288 -> 16; thread = output o (16) x k-segment (16 x 18)
        int o = tid & 15, seg = tid >> 4;
        const float* wp = cW0 + (size_t)j * 288 * 16 + o;
        const float* cond = Bcond + j * 288;
        float s = 0.f;
        int k0 = seg * 18;
        #pragma unroll
        for (int k = 0; k < 18; k++) s += cond[k0 + k] * wp[(k0 + k) * 16];
        partial[seg * 16 + o] = s;
    }
    __syncthreads();
    if (tid < 16) {
        float s = cb0[j * 16 + tid];
        #pragma unroll
        for (int seg = 0; seg < 16; seg++) s += partial[seg * 16 + tid];
        c0s[tid] = sp100(s);
    }
    __syncthreads();
    if (tid < 16) {
        float t = cb1[j * 16 + tid];
        #pragma unroll
        for (int k = 0; k < 16; k++) t += c0s[k] * cW1[j * 256 + k * 16 + tid];
        c1s[tid] = sp100(t);
    }
    __syncthreads();
    if (tid < 4) {
        float u = cb2[j * 4 + tid];
        #pragma unroll
        for (int k = 0; k < 16; k++) u += c1s[k] * cW2[j * 64 + k * 4 + tid];
        g_c[j][tid] = u;
    }

    if (tid < NG) {
        int gi = tid;
        const float* bn = Bneigh + ((j * NG + gi) * 5) * 3;
        float Jt[3] = { bn[0], bn[1], bn[2] };
        float Jc[3] = { bn[3], bn[4], bn[5] };
        float Jo[3] = { bn[6], bn[7], bn[8] };
        float Jp[3] = { bn[9], bn[10], bn[11] };
        int bt = (int)bn[12], bo = (int)bn[13];
        float a_n = ra_elu(alpha[bo * NJ + bt]);
        float a_s = ra_elu(alpha[bt * NJ + bo]);
        float be_n = beta[bo * NJ + bt];
        float be_s = beta[bt * NJ + bo];
        float nb_n = 0.f, nb_s = 0.f;
        for (int d = 0; d < 3; d++) {
            float tn = Jo[d] - Jc[d]; nb_n += tn * tn;
            float ts = Jt[d] - Jc[d]; nb_s += ts * ts;
        }
        nb_n = sqrtf(nb_n); nb_s = sqrtf(nb_s);
        float vn[3], vs[3];
        float f1 = nb_n / (nb_n + nb_s + EPSV);
        for (int d = 0; d < 3; d++) vn[d] = (Jo[d] - Jt[d]) * f1;
        float f2 = nb_s / (nb_n + EPSV);
        for (int d = 0; d < 3; d++) vs[d] = -vn[d] * f2;
        float n_n = 0.f, n_s = 0.f;
        for (int d = 0; d < 3; d++) { n_n += vn[d] * vn[d]; n_s += vs[d] * vs[d]; }
        n_n = sqrtf(n_n); n_s = sqrtf(n_s);
        float cn = a_n / ((n_n + EPSV) * (n_n + EPSV));
        float cs = a_s / ((n_s + EPSV) * (n_s + EPSV));
        float* gg = g_geom[j][gi];
        for (int d = 0; d < 3; d++) gg[d] = Jo[d] - vn[d];
        for (int d = 0; d < 3; d++) gg[3 + d] = vn[d] * cn - vs[d] * cs;
        gg[6] = be_n - be_s;
        for (int d = 0; d < 3; d++) gg[7 + d] = Jp[d];
        for (int d = 0; d < 3; d++) gg[10 + d] = Jc[d];
    }
}

// ---------------------------------------------------------------------------
// Main kernel: 128 points x 1 part per CTA, single-pass fp16 mma,
// register-resident activations, 2 CTAs/SM
// ---------------------------------------------------------------------------
__global__ __launch_bounds__(TPB, 2) void main_kernel(
    const float* __restrict__ pts, const float* __restrict__ Btr, const float* __restrict__ Brot,
    const float* __restrict__ W0, const float* __restrict__ b0,
    const float* __restrict__ b1, const float* __restrict__ b2,
    const float* __restrict__ W3, const float* __restrict__ b3)
{
    extern __shared__ char sm[];
    uint4* wf = (uint4*)sm;                 // [0..2047]=layer1, [2048..4095]=layer2
    float* w0s = (float*)(sm + OFF_F32);
    float* b0s = w0s + 896;
    float* b1s = b0s + 128;
    float* b2s = b1s + 128;
    float* w3s = b2s + 128;

    int tid = threadIdx.x;
    int j = blockIdx.y;
    int v0 = blockIdx.x * MTILE;
    int w = tid >> 5, lane = tid & 31;
    int g = lane >> 2, tig = lane & 3;

    // ---- stage both layers' fragments + w0 + biases ----
    {
        const uint4* s1 = &g_Wf4[0][j][0];
        const uint4* s2 = &g_Wf4[1][j][0];
        #pragma unroll
        for (int i = 0; i < 8; i++) {
            wf[tid + i * TPB] = s1[tid + i * TPB];
            wf[2048 + tid + i * TPB] = s2[tid + i * TPB];
        }
        for (int i = tid; i < 896; i += TPB) w0s[i] = W0[j * 896 + i];
        if (tid < 128) {
            b0s[tid] = b0[j * 128 + tid];
            b1s[tid] = b1[j * 128 + tid];
            b2s[tid] = b2[j * 128 + tid];
            w3s[tid] = W3[j * 128 + tid];
        }
    }

    // ---- geometry: lane L computes row (L & 15) of this warp's 16 rows ----
    int grow = lane & 15;
    int v = v0 + w * 16 + grow;
    int vc = v < NV ? v : NV - 1;
    float xk[7];
    {
        float px = pts[vc * 3 + 0] - Btr[j * 3 + 0];
        float py = pts[vc * 3 + 1] - Btr[j * 3 + 1];
        float pz = pts[vc * 3 + 2] - Btr[j * 3 + 2];
        const float* R = Brot + j * 9;
        float plx = R[0] * px + R[3] * py + R[6] * pz;
        float ply = R[1] * px + R[4] * py + R[7] * pz;
        float plz = R[2] * px + R[5] * py + R[8] * pz;
        float ox = 0.f, oy = 0.f, oz = 0.f;
        #pragma unroll
        for (int gi = 0; gi < NG; gi++) {
            const float* gg = g_geom[j][gi];
            float dx = plx - gg[0], dy = ply - gg[1], dz = plz - gg[2];
            float arg = dx * gg[3] + dy * gg[4] + dz * gg[5] + gg[6];
            float ww = 1.0f / (1.0f + expf(-arg));
            float ax = -gg[7] * ww, ay = -gg[8] * ww, az = -gg[9] * ww;
            float ang = sqrtf(ax * ax + ay * ay + az * az);
            float inv = (ang < 1e-12f) ? 1.0f : (1.0f / ang);
            float ux = ax * inv, uy = ay * inv, uz = az * inv;
            float cc = cosf(ang), ss = sinf(ang);
            float C = 1.0f - cc;
            float qx = plx - gg[10], qy = ply - gg[11], qz = plz - gg[12];
            float rx = (cc + ux * ux * C) * qx + (ux * uy * C - uz * ss) * qy + (ux * uz * C + uy * ss) * qz;
            float ry = (uy * ux * C + uz * ss) * qx + (cc + uy * uy * C) * qy + (uy * uz * C - ux * ss) * qz;
            float rz = (uz * ux * C - uy * ss) * qx + (uz * uy * C + ux * ss) * qy + (cc + uz * uz * C) * qz;
            ox += rx + gg[10] - plx;
            oy += ry + gg[11] - ply;
            oz += rz + gg[12] - plz;
        }
        xk[0] = plx + ox; xk[1] = ply + oy; xk[2] = plz + oz;
        xk[3] = g_c[j][0]; xk[4] = g_c[j][1]; xk[5] = g_c[j][2]; xk[6] = g_c[j][3];
    }

    // redistribute xk: this thread owns rows g and g+8
    float xka[7], xkb[7];
    #pragma unroll
    for (int k = 0; k < 7; k++) {
        xka[k] = __shfl_sync(0xffffffffu, xk[k], g);
        xkb[k] = __shfl_sync(0xffffffffu, xk[k], g + 8);
    }
    __syncthreads();   // weights + biases staged

    // ---- layer0 (7 -> 128) directly into A fragments (registers) ----
    uint32_t frag[8][4];
    #pragma unroll
    for (int kk = 0; kk < 8; kk++) {
        int c = kk * 16 + tig * 2;
        int cols[4] = { c, c + 1, c + 8, c + 9 };
        float sa[4], sb[4];
        #pragma unroll
        for (int ci = 0; ci < 4; ci++) { sa[ci] = b0s[cols[ci]]; sb[ci] = sa[ci]; }
        #pragma unroll
        for (int k = 0; k < 7; k++) {
            #pragma unroll
            for (int ci = 0; ci < 4; ci++) {
                float wv = w0s[k * 128 + cols[ci]];
                sa[ci] += xka[k] * wv;
                sb[ci] += xkb[k] * wv;
            }
        }
        frag[kk][0] = f2h2(sp100f(sa[0]), sp100f(sa[1]));
        frag[kk][1] = f2h2(sp100f(sb[0]), sp100f(sb[1]));
        frag[kk][2] = f2h2(sp100f(sa[2]), sp100f(sa[3]));
        frag[kk][3] = f2h2(sp100f(sb[2]), sp100f(sb[3]));
    }

    // ================= layer 1 =================
    float acc[16][4];
    #pragma unroll
    for (int nt = 0; nt < 16; nt++)
        #pragma unroll
        for (int q = 0; q < 4; q++) acc[nt][q] = 0.f;

    #pragma unroll
    for (int kk = 0; kk < 8; kk++) {
        const uint4* wrow = wf + kk * 256 + lane;
        #pragma unroll
        for (int ntp = 0; ntp < 8; ntp++) {
            uint4 bb = wrow[ntp * 32];
            mma_f16(acc[2 * ntp],     frag[kk], bb.x, bb.y);
            mma_f16(acc[2 * ntp + 1], frag[kk], bb.z, bb.w);
        }
    }

    // ---- epilogue layer1: bias + softplus -> layer-2 A fragments ----
    #pragma unroll
    for (int kk = 0; kk < 8; kk++) {
        int n0 = kk * 16 + tig * 2;
        int n1 = n0 + 8;
        frag[kk][0] = f2h2(sp100f(acc[2 * kk][0] + b1s[n0]), sp100f(acc[2 * kk][1] + b1s[n0 + 1]));
        frag[kk][1] = f2h2(sp100f(acc[2 * kk][2] + b1s[n0]), sp100f(acc[2 * kk][3] + b1s[n0 + 1]));
        frag[kk][2] = f2h2(sp100f(acc[2 * kk + 1][0] + b1s[n1]), sp100f(acc[2 * kk + 1][1] + b1s[n1 + 1]));
        frag[kk][3] = f2h2(sp100f(acc[2 * kk + 1][2] + b1s[n1]), sp100f(acc[2 * kk + 1][3] + b1s[n1 + 1]));
    }

    // ================= layer 2 =================
    #pragma unroll
    for (int nt = 0; nt < 16; nt++)
        #pragma unroll
        for (int q = 0; q < 4; q++) acc[nt][q] = 0.f;

    #pragma unroll
    for (int kk = 0; kk < 8; kk++) {
        const uint4* wrow = wf + 2048 + kk * 256 + lane;
        #pragma unroll
        for (int ntp = 0; ntp < 8; ntp++) {
            uint4 bb = wrow[ntp * 32];
            mma_f16(acc[2 * ntp],     frag[kk], bb.x, bb.y);
            mma_f16(acc[2 * ntp + 1], frag[kk], bb.z, bb.w);
        }
    }

    // ---- epilogue layer2 + layer3 dot + quad reduce ----
    {
        float dot0 = 0.f, dot1 = 0.f;
        #pragma unroll
        for (int nt = 0; nt < 16; nt++) {
            int n = nt * 8 + tig * 2;
            dot0 += sp100f(acc[nt][0] + b2s[n]) * w3s[n];
            dot0 += sp100f(acc[nt][1] + b2s[n + 1]) * w3s[n + 1];
            dot1 += sp100f(acc[nt][2] + b2s[n]) * w3s[n];
            dot1 += sp100f(acc[nt][3] + b2s[n + 1]) * w3s[n + 1];
        }
        dot0 += __shfl_xor_sync(0xffffffffu, dot0, 1);
        dot0 += __shfl_xor_sync(0xffffffffu, dot0, 2);
        dot1 += __shfl_xor_sync(0xffffffffu, dot1, 1);
        dot1 += __shfl_xor_sync(0xffffffffu, dot1, 2);
        if (tig == 0) {
            float bb = b3[j];
            int m0 = w * 16 + g;
            int va = v0 + m0;
            int vb = v0 + m0 + 8;
            if (va < NV) g_pred[j][va] = dot0 + bb;
            if (vb < NV) g_pred[j][vb] = dot1 + bb;
        }
    }
}

// ---------------------------------------------------------------------------
// Softmin blend over parts
// ---------------------------------------------------------------------------
__global__ void softmin_kernel(float* __restrict__ out) {
    int v = blockIdx.x * blockDim.x + threadIdx.x;
    if (v >= NV) return;
    float p[NJ];
    float mn = 3.0e38f;
    #pragma unroll
    for (int j = 0; j < NJ; j++) { p[j] = g_pred[j][v]; mn = fminf(mn, p[j]); }
    float se = 0.f, sd = 0.f;
    #pragma unroll
    for (int j = 0; j < NJ; j++) {
        float d = p[j] - mn;
        float e = expf(-200.0f * d);
        se += e;
        sd += d * e;
    }
    out[v] = sd / se + mn;
}

extern "C" void kernel_launch(void* const* d_in, const int* in_sizes, int n_in,
                              void* d_out, int out_size)
{
    const float* pts    = (const float*)d_in[0];
    const float* Bcond  = (const float*)d_in[1];
    const float* Btr    = (const float*)d_in[2];
    const float* Brot   = (const float*)d_in[3];
    const float* Bneigh = (const float*)d_in[4];
    const float* alpha  = (const float*)d_in[5];
    const float* beta   = (const float*)d_in[6];
    const float* cW0 = (const float*)d_in[7];
    const float* cb0 = (const float*)d_in[8];
    const float* cW1 = (const float*)d_in[9];
    const float* cb1 = (const float*)d_in[10];
    const float* cW2 = (const float*)d_in[11];
    const float* cb2 = (const float*)d_in[12];
    const float* W0  = (const float*)d_in[13];
    const float* b0  = (const float*)d_in[14];
    const float* W1  = (const float*)d_in[15];
    const float* b1  = (const float*)d_in[16];
    const float* W2  = (const float*)d_in[17];
    const float* b2  = (const float*)d_in[18];
    const float* W3  = (const float*)d_in[19];
    const float* b3  = (const float*)d_in[20];

    cudaFuncSetAttribute(setup_kernel, cudaFuncAttributeMaxDynamicSharedMemorySize, SMEM_SETUP);
    cudaFuncSetAttribute(main_kernel, cudaFuncAttributeMaxDynamicSharedMemorySize, SMEM_MAIN);

    setup_kernel<<<3 * NJ, 256, SMEM_SETUP>>>(W1, W2, Bcond, Bneigh, alpha, beta,
                                              cW0, cb0, cW1, cb1, cW2, cb2);

    dim3 grid((NV + MTILE - 1) / MTILE, NJ);
    main_kernel<<<grid, TPB, SMEM_MAIN>>>(pts, Btr, Brot, W0, b0, b1, b2, W3, b3);

    softmin_kernel<<<(NV + 255) / 256, 256>>>((float*)d_out);
}